// round 12
// baseline (speedup 1.0000x reference)
#include <cuda_runtime.h>
#include <cuda_bf16.h>

#define NN 50000     // nodes
#define NE 10000     // edges
#define NZ 800000    // nnz
#define FIN 128
#define F4 32        // float4 per feature row
#define HIDN 512
#define ECAP 192     // max nodes per edge bucket (Poisson(80), P(>192) ~ 1e-25)
#define VCAP 64      // max edges per node bucket (Poisson(16), P(>64) ~ 1e-20)
#define KORD 10      // Chebyshev order (theta has KORD+1 entries)
#define GM 128       // GEMM CTA tile M (rows per CTA)
#define GNT 128      // GEMM column tile (4 tiles cover HIDN=512)
#define STRW 68      // SMEM row stride in 32-bit words (64 data + 4 pad -> conflict-free frags)
#define PGRID 1184   // persistent grid (148 SMs x 8 blocks)

// ---------------- static device scratch (no allocation allowed) ----------------
__device__ int   g_flag32 = 0;    // sticky: 1 if hyperedge_index detected as int32
__device__ int   g_cnt_e[NE];
__device__ int   g_cnt_v[NN];
__device__ int   g_ecol[NE * ECAP];   // node indices, bucketed by edge (7.7 MB)
__device__ int   g_vcol[NN * VCAP];   // edge indices, bucketed by node (12.8 MB)
__device__ float g_dvis[NN];
__device__ float g_dew[NE];
__device__ float4 g_me[NE * F4];      // 5.1 MB
__device__ float4 g_buf0[NN * F4];    // 25.6 MB  (Clenshaw b_j, even parity)
__device__ float4 g_buf1[NN * F4];    // 25.6 MB  (Clenshaw b_j, odd parity)
__device__ __nv_bfloat16 g_ah[NN * FIN];     // 12.8 MB  Clenshaw result, bf16 hi
__device__ __nv_bfloat16 g_al[NN * FIN];     // 12.8 MB  Clenshaw result, bf16 lo
__device__ __nv_bfloat16 g_wh[HIDN * FIN];   // W hi
__device__ __nv_bfloat16 g_wl[HIDN * FIN];   // W lo

// ---------------- generic helpers ----------------
__device__ __forceinline__ float4 f4z() { return make_float4(0.f, 0.f, 0.f, 0.f); }
__device__ __forceinline__ void f4fma(float4& a, float s, const float4& v) {
    a.x = fmaf(s, v.x, a.x); a.y = fmaf(s, v.y, a.y);
    a.z = fmaf(s, v.z, a.z); a.w = fmaf(s, v.w, a.w);
}
__device__ __forceinline__ void f4add(float4& a, const float4& v) {
    a.x += v.x; a.y += v.y; a.z += v.z; a.w += v.w;
}
__device__ __forceinline__ int clampi(int v, int lo, int hi) {
    return min(max(v, lo), hi);
}
__device__ __forceinline__ void get_pair(const void* he, int i, int& node, int& edge) {
    if (g_flag32 == 0) { // int64
        node = (int)((const long long*)he)[i];
        edge = (int)((const long long*)he)[NZ + i];
    } else {             // int32
        node = ((const int*)he)[i];
        edge = ((const int*)he)[NZ + i];
    }
    node = clampi(node, 0, NN - 1);
    edge = clampi(edge, 0, NE - 1);
}

// mma.sync bf16 (baseline PTX, works on plain sm_103 target)
__device__ __forceinline__ void mma_bf16(float* d, const unsigned* a, const unsigned* b) {
    asm volatile(
        "mma.sync.aligned.m16n8k16.row.col.f32.bf16.bf16.f32 "
        "{%0,%1,%2,%3}, {%4,%5,%6,%7}, {%8,%9}, {%0,%1,%2,%3};"
        : "+f"(d[0]), "+f"(d[1]), "+f"(d[2]), "+f"(d[3])
        : "r"(a[0]), "r"(a[1]), "r"(a[2]), "r"(a[3]), "r"(b[0]), "r"(b[1]));
}

// cp.async 16B with zero-fill when sz==0 (baseline PTX, sm_80+)
__device__ __forceinline__ void cp_async16(unsigned dst, const void* src, unsigned sz) {
    asm volatile("cp.async.cg.shared.global [%0], [%1], 16, %2;"
                 :: "r"(dst), "l"(src), "r"(sz) : "memory");
}
#define CP_COMMIT() asm volatile("cp.async.commit_group;" ::: "memory")
#define CP_WAIT0()  asm volatile("cp.async.wait_group 0;" ::: "memory")

// ---------------- launch 0: zero counters + dtype detection ----------------
__global__ void k_zero(const int* __restrict__ he32) {
    int i = blockIdx.x * blockDim.x + threadIdx.x;
    if (i < 4096) {
        if (he32[2 * i + 1] != 0) atomicOr(&g_flag32, 1);
    }
    if (i < NE) g_cnt_e[i] = 0;
    if (i < NN) g_cnt_v[i] = 0;
}

// ---------------- launch 1: single-pass bucketed CSR build (no float atomics) ----------------
__global__ void k_build(const void* __restrict__ he) {
    int i = blockIdx.x * blockDim.x + threadIdx.x;
    if (i >= NZ) return;
    int node, edge;
    get_pair(he, i, node, edge);
    int p = atomicAdd(&g_cnt_e[edge], 1);
    if (p < ECAP) g_ecol[edge * ECAP + p] = node;
    int q = atomicAdd(&g_cnt_v[node], 1);
    if (q < VCAP) g_vcol[node * VCAP + q] = edge;
}

// ---------------- launch 2: norm factors (dvis from buckets) + Clenshaw init + W split ----------------
__global__ void k_degs_init(const float* __restrict__ ew, const float4* __restrict__ x4,
                            const float* __restrict__ theta, const float* __restrict__ W) {
    int i = blockIdx.x * blockDim.x + threadIdx.x;
    if (i < NE) {
        float de = (float)g_cnt_e[i];
        g_dew[i] = (de > 0.f) ? (ew[i] / fmaxf(de, 1e-12f)) : 0.f;
    }
    if (i < NN) {
        // d_v = sum of ew over this node's incident edges, gathered from buckets (no atomics)
        int cnt = min(g_cnt_v[i], VCAP);
        const int* __restrict__ col = g_vcol + i * VCAP;
        float dv = 0.f;
        for (int q = 0; q < cnt; q++) dv += __ldg(&ew[col[q]]);
        g_dvis[i] = (dv > 0.f) ? rsqrtf(fmaxf(dv, 1e-12f)) : 0.f;
    }
    if (i < HIDN * FIN) {
        float v = W[i];
        __nv_bfloat16 h = __float2bfloat16(v);
        g_wh[i] = h;
        g_wl[i] = __float2bfloat16(v - __bfloat162float(h));
    }
    if (i < NN * F4) {
        float th = theta[KORD];
        float4 v = x4[i];
        v.x *= th; v.y *= th; v.z *= th; v.w *= th;
        g_buf0[i] = v;   // b_10 -> buf[10&1] = buf0
    }
}

// ---------------- hot loop: edge aggregation (phase A), persistent, 4 warps/edge ----------------
__global__ void k_edge(int j) {
    const float4* __restrict__ t = ((j + 1) & 1) ? g_buf1 : g_buf0;
    __shared__ float4 part[8][32];
    int tid = threadIdx.x;
    int wid = tid >> 5;
    int lane = tid & 31;
    int sub = wid >> 2;           // 0..1: which edge of this iteration's pair
    int chunk = wid & 3;          // 0..3: stride-4 chunk

    for (int base = blockIdx.x * 2; base < NE; base += gridDim.x * 2) {
        int e_idx = base + sub;   // NE even, base <= NE-2 -> e_idx < NE always
        const int* __restrict__ col = g_ecol + e_idx * ECAP;
        int deg = min(g_cnt_e[e_idx], ECAP);

        float4 a0 = f4z(), a1 = f4z(), a2 = f4z(), a3 = f4z();
        int jj = chunk;
        for (; jj + 12 < deg; jj += 16) {
            int n0 = col[jj], n1 = col[jj + 4], n2 = col[jj + 8], n3 = col[jj + 12];
            float w0 = g_dvis[n0], w1 = g_dvis[n1], w2 = g_dvis[n2], w3 = g_dvis[n3];
            float4 v0 = __ldg(&t[n0 * F4 + lane]);
            float4 v1 = __ldg(&t[n1 * F4 + lane]);
            float4 v2 = __ldg(&t[n2 * F4 + lane]);
            float4 v3 = __ldg(&t[n3 * F4 + lane]);
            f4fma(a0, w0, v0); f4fma(a1, w1, v1); f4fma(a2, w2, v2); f4fma(a3, w3, v3);
        }
        for (; jj < deg; jj += 4) {
            int n0 = col[jj];
            float w0 = g_dvis[n0];
            float4 v0 = __ldg(&t[n0 * F4 + lane]);
            f4fma(a0, w0, v0);
        }
        float4 a;
        a.x = (a0.x + a1.x) + (a2.x + a3.x);
        a.y = (a0.y + a1.y) + (a2.y + a3.y);
        a.z = (a0.z + a1.z) + (a2.z + a3.z);
        a.w = (a0.w + a1.w) + (a2.w + a3.w);
        part[wid][lane] = a;
        __syncthreads();

        if (chunk == 0) {
            int b = sub * 4;
            float4 p0 = part[b][lane], p1 = part[b + 1][lane];
            float4 p2 = part[b + 2][lane], p3 = part[b + 3][lane];
            float dw = g_dew[e_idx];
            float4 o;
            o.x = dw * ((p0.x + p1.x) + (p2.x + p3.x));
            o.y = dw * ((p0.y + p1.y) + (p2.y + p3.y));
            o.z = dw * ((p0.z + p1.z) + (p2.z + p3.z));
            o.w = dw * ((p0.w + p1.w) + (p2.w + p3.w));
            g_me[e_idx * F4 + lane] = o;
        }
        __syncthreads();          // WAR: part[] reused next iteration
    }
}

// ---------------- hot loop: node aggregation + Clenshaw step (phase B), persistent ----------------
// j>=1: b_j = theta[j]*x - 2*dvis*sum - b_{j+2}  (in-place in buf[j&1])
// j==0: out = theta[0]*x - dvis*sum - b_2, split to bf16 hi/lo for the GEMM
__global__ void k_node(const float4* __restrict__ x4, const float* __restrict__ theta, int j) {
    int lane = threadIdx.x & 31;
    int warps_total = gridDim.x * (blockDim.x >> 5);
    int w0 = (blockIdx.x * blockDim.x + threadIdx.x) >> 5;

    for (int w = w0; w < NN; w += warps_total) {
        const int* __restrict__ col = g_vcol + w * VCAP;
        int e = min(g_cnt_v[w], VCAP);
        float4 a0 = f4z(), a1 = f4z(), a2 = f4z(), a3 = f4z();
        int jj = 0;
        for (; jj + 4 <= e; jj += 4) {
            int e0 = col[jj], e1 = col[jj + 1], e2 = col[jj + 2], e3 = col[jj + 3];
            float4 v0 = __ldg(&g_me[e0 * F4 + lane]);
            float4 v1 = __ldg(&g_me[e1 * F4 + lane]);
            float4 v2 = __ldg(&g_me[e2 * F4 + lane]);
            float4 v3 = __ldg(&g_me[e3 * F4 + lane]);
            f4add(a0, v0); f4add(a1, v1); f4add(a2, v2); f4add(a3, v3);
        }
        for (; jj < e; jj++) {
            int e0 = col[jj];
            f4add(a0, __ldg(&g_me[e0 * F4 + lane]));
        }
        float4 sum;
        sum.x = (a0.x + a1.x) + (a2.x + a3.x);
        sum.y = (a0.y + a1.y) + (a2.y + a3.y);
        sum.z = (a0.z + a1.z) + (a2.z + a3.z);
        sum.w = (a0.w + a1.w) + (a2.w + a3.w);

        float dv = g_dvis[w];
        int idx = w * F4 + lane;
        float th = theta[j];
        float4 xv = __ldg(&x4[idx]);

        float m = (j == 0) ? -dv : -2.f * dv;
        float4 r;
        r.x = fmaf(th, xv.x, m * sum.x);
        r.y = fmaf(th, xv.y, m * sum.y);
        r.z = fmaf(th, xv.z, m * sum.z);
        r.w = fmaf(th, xv.w, m * sum.w);

        if (j == 0) {
            float4 old = g_buf0[idx];                  // b_2
            r.x -= old.x; r.y -= old.y; r.z -= old.z; r.w -= old.w;
            __nv_bfloat16 h0 = __float2bfloat16(r.x);
            __nv_bfloat16 h1 = __float2bfloat16(r.y);
            __nv_bfloat16 h2 = __float2bfloat16(r.z);
            __nv_bfloat16 h3 = __float2bfloat16(r.w);
            ushort4 hh = make_ushort4(__bfloat16_as_ushort(h0), __bfloat16_as_ushort(h1),
                                      __bfloat16_as_ushort(h2), __bfloat16_as_ushort(h3));
            ushort4 ll = make_ushort4(
                __bfloat16_as_ushort(__float2bfloat16(r.x - __bfloat162float(h0))),
                __bfloat16_as_ushort(__float2bfloat16(r.y - __bfloat162float(h1))),
                __bfloat16_as_ushort(__float2bfloat16(r.z - __bfloat162float(h2))),
                __bfloat16_as_ushort(__float2bfloat16(r.w - __bfloat162float(h3))));
            *(ushort4*)(g_ah + 4 * (size_t)idx) = hh;
            *(ushort4*)(g_al + 4 * (size_t)idx) = ll;
        } else {
            float4* buf = (j & 1) ? g_buf1 : g_buf0;
            if (j != KORD - 1) {
                float4 old = buf[idx];
                r.x -= old.x; r.y -= old.y; r.z -= old.z; r.w -= old.w;
            }
            buf[idx] = r;
        }
    }
}

// ---------------- GEMM (mma.sync bf16x3, cp.async pipelined) ----------------
// C = relu(A[N,128] @ W[512,128]^T + b). One CTA per 128-row block (grid=391).
// A hi/lo staged ONCE via cp.async; B tiles (128 cols) double-buffered, prefetch
// of tile ct+1 overlaps compute of tile ct. 8 warps as 4m x 2n; warp tile 32x64.
// D(fp32) = Ah*Wh + Ah*Wl + Al*Wh (Al*Wl dropped, ~2^-18 relative).
__global__ void __launch_bounds__(256) k_mma(const float* __restrict__ bias,
                                             float* __restrict__ C) {
    extern __shared__ unsigned sm[];
    unsigned* Ahs = sm;                              // GM*STRW words
    unsigned* Als = Ahs + GM * STRW;
    unsigned* Bbuf = Als + GM * STRW;                // 2 buffers x (Bh + Bl), each GNT*STRW
    int tid = threadIdx.x;
    int row0 = blockIdx.x * GM;
    unsigned smb = (unsigned)__cvta_generic_to_shared(sm);

    // --- stage A (hi/lo) via cp.async, 16B chunks, zero-fill OOB rows ---
    {
        const char* Ah8 = (const char*)g_ah;
        const char* Al8 = (const char*)g_al;
        for (int i = tid; i < GM * 16; i += 256) {
            int r = i >> 4, c4 = i & 15;             // 16 chunks of 16B per 256B row
            int gr = row0 + r;
            unsigned sz = (gr < NN) ? 16u : 0u;
            size_t gofs = (size_t)gr * 256 + c4 * 16;
            unsigned dofs = (unsigned)((r * STRW + c4 * 4) * 4);
            cp_async16(smb + ((unsigned)((char*)Ahs - (char*)sm)) + dofs, Ah8 + gofs, sz);
            cp_async16(smb + ((unsigned)((char*)Als - (char*)sm)) + dofs, Al8 + gofs, sz);
        }
    }
    // --- prefetch B tile 0 into buffer 0 (same commit group as A) ---
    const char* Wh8 = (const char*)g_wh;
    const char* Wl8 = (const char*)g_wl;
    unsigned bbase = (unsigned)((char*)Bbuf - (char*)sm);
    {
        for (int i = tid; i < GNT * 16; i += 256) {
            int r = i >> 4, c4 = i & 15;
            size_t gofs = (size_t)r * 256 + c4 * 16;   // tile 0: col0 = 0
            unsigned dofs = (unsigned)((r * STRW + c4 * 4) * 4);
            cp_async16(smb + bbase + dofs, Wh8 + gofs, 16u);
            cp_async16(smb + bbase + (unsigned)(GNT * STRW * 4) + dofs, Wl8 + gofs, 16u);
        }
    }
    CP_COMMIT();

    int wid = tid >> 5, lane = tid & 31;
    int wm = wid & 3, wn = wid >> 2;       // warp grid 4 (m) x 2 (n)
    int lr = lane >> 2, lc = lane & 3;     // m16n8k16 lane decomposition

    for (int ct = 0; ct < HIDN / GNT; ct++) {
        CP_WAIT0();
        __syncthreads();                   // tile ct data visible; compute ct-1 finished everywhere

        // prefetch tile ct+1 into the alternate buffer, overlapped with compute of ct
        if (ct + 1 < HIDN / GNT) {
            unsigned bo = bbase + (unsigned)(((ct + 1) & 1) * 2 * GNT * STRW * 4);
            size_t colbase = (size_t)(ct + 1) * GNT * 256;
            for (int i = tid; i < GNT * 16; i += 256) {
                int r = i >> 4, c4 = i & 15;
                size_t gofs = colbase + (size_t)r * 256 + c4 * 16;
                unsigned dofs = (unsigned)((r * STRW + c4 * 4) * 4);
                cp_async16(smb + bo + dofs, Wh8 + gofs, 16u);
                cp_async16(smb + bo + (unsigned)(GNT * STRW * 4) + dofs, Wl8 + gofs, 16u);
            }
            CP_COMMIT();
        }

        const unsigned* Bhs = Bbuf + (ct & 1) * 2 * GNT * STRW;
        const unsigned* Bls = Bhs + GNT * STRW;
        int col0 = ct * GNT;

        float acc[2][8][4];
        #pragma unroll
        for (int mf = 0; mf < 2; mf++)
            #pragma unroll
            for (int nf = 0; nf < 8; nf++)
                #pragma unroll
                for (int q = 0; q < 4; q++) acc[mf][nf][q] = 0.f;

        const unsigned* Aps[3] = { Ahs, Ahs, Als };
        const unsigned* Bps[3] = { Bhs, Bls, Bhs };
        #pragma unroll
        for (int ps = 0; ps < 3; ps++) {
            const unsigned* At = Aps[ps];
            const unsigned* Bt = Bps[ps];
            #pragma unroll
            for (int kk = 0; kk < 8; kk++) {   // 8 k-chunks of 16 bf16 (8 words)
                unsigned afr[2][4];
                #pragma unroll
                for (int mf = 0; mf < 2; mf++) {
                    const unsigned* p = At + (wm * 32 + mf * 16 + lr) * STRW + kk * 8 + lc;
                    afr[mf][0] = p[0];
                    afr[mf][1] = p[8 * STRW];
                    afr[mf][2] = p[4];
                    afr[mf][3] = p[8 * STRW + 4];
                }
                #pragma unroll
                for (int nf = 0; nf < 8; nf++) {
                    unsigned bfr[2];
                    const unsigned* p = Bt + (wn * 64 + nf * 8 + lr) * STRW + kk * 8 + lc;
                    bfr[0] = p[0];
                    bfr[1] = p[4];
                    mma_bf16(acc[0][nf], afr[0], bfr);
                    mma_bf16(acc[1][nf], afr[1], bfr);
                }
            }
        }

        // epilogue for this column tile: bias + relu, float2 stores
        #pragma unroll
        for (int mf = 0; mf < 2; mf++) {
            #pragma unroll
            for (int nf = 0; nf < 8; nf++) {
                int r = row0 + wm * 32 + mf * 16 + lr;
                int c = col0 + wn * 64 + nf * 8 + lc * 2;
                float2 bb = *(const float2*)&bias[c];
                if (r < NN) {
                    float2 o;
                    o.x = fmaxf(acc[mf][nf][0] + bb.x, 0.f);
                    o.y = fmaxf(acc[mf][nf][1] + bb.y, 0.f);
                    *(float2*)&C[(size_t)r * HIDN + c] = o;
                }
                int r2 = r + 8;
                if (r2 < NN) {
                    float2 o;
                    o.x = fmaxf(acc[mf][nf][2] + bb.x, 0.f);
                    o.y = fmaxf(acc[mf][nf][3] + bb.y, 0.f);
                    *(float2*)&C[(size_t)r2 * HIDN + c] = o;
                }
            }
        }
    }
}

// ---------------- launch ----------------
extern "C" void kernel_launch(void* const* d_in, const int* in_sizes, int n_in,
                              void* d_out, int out_size) {
    const float* x     = (const float*)d_in[0];
    const void*  he    = (const void*)d_in[1];
    const float* ew    = (const float*)d_in[2];
    const float* theta = (const float*)d_in[3];
    const float* w1    = (const float*)d_in[4];
    const float* b1    = (const float*)d_in[5];
    float*       out   = (float*)d_out;

    const int TB = 256;
    k_zero<<<(NN + TB - 1) / TB, TB>>>((const int*)he);
    k_build<<<(NZ + TB - 1) / TB, TB>>>(he);
    k_degs_init<<<(NN * F4 + TB - 1) / TB, TB>>>(ew, (const float4*)x, theta, w1);

    for (int j = KORD - 1; j >= 0; j--) {
        k_edge<<<PGRID, TB>>>(j);
        k_node<<<PGRID, TB>>>((const float4*)x, theta, j);
    }

    // SMEM: A (hi+lo) + 2 x B (hi+lo) = (2 + 4) * 128 * STRW words
    const int SMEM_MMA = (2 * GM * STRW + 4 * GNT * STRW) * 4;  // 208896 B
    cudaFuncSetAttribute(k_mma, cudaFuncAttributeMaxDynamicSharedMemorySize, SMEM_MMA);
    k_mma<<<(NN + GM - 1) / GM, 256, SMEM_MMA>>>(b1, out);
}

// round 13
// speedup vs baseline: 1.1906x; 1.1906x over previous
#include <cuda_runtime.h>
#include <cuda_bf16.h>

#define NN 50000     // nodes
#define NE 10000     // edges
#define NZ 800000    // nnz
#define FIN 128
#define F4 32        // float4 per feature row
#define HIDN 512
#define ECAP 192     // max nodes per edge bucket (Poisson(80), P(>192) ~ 1e-25)
#define VCAP 64      // max edges per node bucket (Poisson(16), P(>64) ~ 1e-20)
#define KORD 10      // Chebyshev order (theta has KORD+1 entries)
#define GM 128       // GEMM CTA tile M (rows per CTA)
#define GNT 128      // GEMM column tile (4 tiles cover HIDN=512)
#define STRW 68      // SMEM row stride in 32-bit words (64 data + 4 pad -> conflict-free frags)

// ---------------- static device scratch (no allocation allowed) ----------------
__device__ int   g_flag32 = 0;    // sticky: 1 if hyperedge_index detected as int32
__device__ int   g_cnt_e[NE];
__device__ int   g_cnt_v[NN];
__device__ int   g_ecol[NE * ECAP];   // node indices, bucketed by edge (7.7 MB)
__device__ int   g_vcol[NN * VCAP];   // edge indices, bucketed by node (12.8 MB)
__device__ float g_dvis[NN];
__device__ float g_dew[NE];
__device__ float4 g_me[NE * F4];      // 5.1 MB
__device__ float4 g_buf0[NN * F4];    // 25.6 MB  (Clenshaw b_j, even parity)
__device__ float4 g_buf1[NN * F4];    // 25.6 MB  (Clenshaw b_j, odd parity)
__device__ __nv_bfloat16 g_ah[NN * FIN];     // 12.8 MB  Clenshaw result, bf16 hi
__device__ __nv_bfloat16 g_al[NN * FIN];     // 12.8 MB  Clenshaw result, bf16 lo
__device__ __nv_bfloat16 g_wh[HIDN * FIN];   // W hi
__device__ __nv_bfloat16 g_wl[HIDN * FIN];   // W lo

// ---------------- generic helpers ----------------
__device__ __forceinline__ float4 f4z() { return make_float4(0.f, 0.f, 0.f, 0.f); }
__device__ __forceinline__ void f4fma(float4& a, float s, const float4& v) {
    a.x = fmaf(s, v.x, a.x); a.y = fmaf(s, v.y, a.y);
    a.z = fmaf(s, v.z, a.z); a.w = fmaf(s, v.w, a.w);
}
__device__ __forceinline__ void f4add(float4& a, const float4& v) {
    a.x += v.x; a.y += v.y; a.z += v.z; a.w += v.w;
}
__device__ __forceinline__ int clampi(int v, int lo, int hi) {
    return min(max(v, lo), hi);
}
__device__ __forceinline__ void get_pair(const void* he, int i, int& node, int& edge) {
    if (g_flag32 == 0) { // int64
        node = (int)((const long long*)he)[i];
        edge = (int)((const long long*)he)[NZ + i];
    } else {             // int32
        node = ((const int*)he)[i];
        edge = ((const int*)he)[NZ + i];
    }
    node = clampi(node, 0, NN - 1);
    edge = clampi(edge, 0, NE - 1);
}

// mma.sync bf16 (baseline PTX, works on plain sm_103 target)
__device__ __forceinline__ void mma_bf16(float* d, const unsigned* a, const unsigned* b) {
    asm volatile(
        "mma.sync.aligned.m16n8k16.row.col.f32.bf16.bf16.f32 "
        "{%0,%1,%2,%3}, {%4,%5,%6,%7}, {%8,%9}, {%0,%1,%2,%3};"
        : "+f"(d[0]), "+f"(d[1]), "+f"(d[2]), "+f"(d[3])
        : "r"(a[0]), "r"(a[1]), "r"(a[2]), "r"(a[3]), "r"(b[0]), "r"(b[1]));
}

// cp.async 16B with zero-fill when sz==0 (baseline PTX, sm_80+)
__device__ __forceinline__ void cp_async16(unsigned dst, const void* src, unsigned sz) {
    asm volatile("cp.async.cg.shared.global [%0], [%1], 16, %2;"
                 :: "r"(dst), "l"(src), "r"(sz) : "memory");
}
#define CP_COMMIT() asm volatile("cp.async.commit_group;" ::: "memory")
#define CP_WAIT0()  asm volatile("cp.async.wait_group 0;" ::: "memory")

// ---------------- launch 0: zero counters + dtype detection ----------------
__global__ void k_zero(const int* __restrict__ he32) {
    int i = blockIdx.x * blockDim.x + threadIdx.x;
    if (i < 4096) {
        if (he32[2 * i + 1] != 0) atomicOr(&g_flag32, 1);
    }
    if (i < NE) g_cnt_e[i] = 0;
    if (i < NN) g_cnt_v[i] = 0;
}

// ---------------- launch 1: single-pass bucketed CSR build (no float atomics) ----------------
__global__ void k_build(const void* __restrict__ he) {
    int i = blockIdx.x * blockDim.x + threadIdx.x;
    if (i >= NZ) return;
    int node, edge;
    get_pair(he, i, node, edge);
    int p = atomicAdd(&g_cnt_e[edge], 1);
    if (p < ECAP) g_ecol[edge * ECAP + p] = node;
    int q = atomicAdd(&g_cnt_v[node], 1);
    if (q < VCAP) g_vcol[node * VCAP + q] = edge;
}

// ---------------- launch 2: norm factors (dvis from buckets) + Clenshaw init + W split ----------------
__global__ void k_degs_init(const float* __restrict__ ew, const float4* __restrict__ x4,
                            const float* __restrict__ theta, const float* __restrict__ W) {
    int i = blockIdx.x * blockDim.x + threadIdx.x;
    if (i < NE) {
        float de = (float)g_cnt_e[i];
        g_dew[i] = (de > 0.f) ? (ew[i] / fmaxf(de, 1e-12f)) : 0.f;
    }
    if (i < NN) {
        // d_v = sum of ew over this node's incident edges, gathered from buckets (no atomics)
        int cnt = min(g_cnt_v[i], VCAP);
        const int* __restrict__ col = g_vcol + i * VCAP;
        float dv = 0.f;
        for (int q = 0; q < cnt; q++) dv += __ldg(&ew[col[q]]);
        g_dvis[i] = (dv > 0.f) ? rsqrtf(fmaxf(dv, 1e-12f)) : 0.f;
    }
    if (i < HIDN * FIN) {
        float v = W[i];
        __nv_bfloat16 h = __float2bfloat16(v);
        g_wh[i] = h;
        g_wl[i] = __float2bfloat16(v - __bfloat162float(h));
    }
    if (i < NN * F4) {
        float th = theta[KORD];
        float4 v = x4[i];
        v.x *= th; v.y *= th; v.z *= th; v.w *= th;
        g_buf0[i] = v;   // b_10 -> buf[10&1] = buf0
    }
}

// ---------------- hot loop: edge aggregation (phase A), 4 warps per edge ----------------
__global__ void k_edge(int j) {
    const float4* __restrict__ t = ((j + 1) & 1) ? g_buf1 : g_buf0;
    __shared__ float4 part[8][32];
    int tid = threadIdx.x;
    int wid = tid >> 5;
    int lane = tid & 31;
    int sub = wid >> 2;
    int chunk = wid & 3;
    int e_idx = blockIdx.x * 2 + sub;

    const int* __restrict__ col = g_ecol + e_idx * ECAP;
    int deg = min(g_cnt_e[e_idx], ECAP);

    float4 a0 = f4z(), a1 = f4z(), a2 = f4z(), a3 = f4z();
    int jj = chunk;
    for (; jj + 12 < deg; jj += 16) {
        int n0 = col[jj], n1 = col[jj + 4], n2 = col[jj + 8], n3 = col[jj + 12];
        float w0 = g_dvis[n0], w1 = g_dvis[n1], w2 = g_dvis[n2], w3 = g_dvis[n3];
        float4 v0 = __ldg(&t[n0 * F4 + lane]);
        float4 v1 = __ldg(&t[n1 * F4 + lane]);
        float4 v2 = __ldg(&t[n2 * F4 + lane]);
        float4 v3 = __ldg(&t[n3 * F4 + lane]);
        f4fma(a0, w0, v0); f4fma(a1, w1, v1); f4fma(a2, w2, v2); f4fma(a3, w3, v3);
    }
    for (; jj < deg; jj += 4) {
        int n0 = col[jj];
        float w0 = g_dvis[n0];
        float4 v0 = __ldg(&t[n0 * F4 + lane]);
        f4fma(a0, w0, v0);
    }
    float4 a;
    a.x = (a0.x + a1.x) + (a2.x + a3.x);
    a.y = (a0.y + a1.y) + (a2.y + a3.y);
    a.z = (a0.z + a1.z) + (a2.z + a3.z);
    a.w = (a0.w + a1.w) + (a2.w + a3.w);
    part[wid][lane] = a;
    __syncthreads();

    if (chunk == 0) {
        int b = sub * 4;
        float4 p0 = part[b][lane], p1 = part[b + 1][lane];
        float4 p2 = part[b + 2][lane], p3 = part[b + 3][lane];
        float dw = g_dew[e_idx];
        float4 o;
        o.x = dw * ((p0.x + p1.x) + (p2.x + p3.x));
        o.y = dw * ((p0.y + p1.y) + (p2.y + p3.y));
        o.z = dw * ((p0.z + p1.z) + (p2.z + p3.z));
        o.w = dw * ((p0.w + p1.w) + (p2.w + p3.w));
        g_me[e_idx * F4 + lane] = o;
    }
}

// ---------------- hot loop: node aggregation + Clenshaw step (phase B) ----------------
// j>=1: b_j = theta[j]*x - 2*dvis*sum - b_{j+2}  (in-place in buf[j&1])
// j==0: out = theta[0]*x - dvis*sum - b_2, split to bf16 hi/lo for the GEMM
__global__ void k_node(const float4* __restrict__ x4, const float* __restrict__ theta, int j) {
    int w = (blockIdx.x * blockDim.x + threadIdx.x) >> 5;
    int lane = threadIdx.x & 31;
    if (w >= NN) return;
    const int* __restrict__ col = g_vcol + w * VCAP;
    int e = min(g_cnt_v[w], VCAP);
    float4 a0 = f4z(), a1 = f4z(), a2 = f4z(), a3 = f4z();
    int jj = 0;
    for (; jj + 4 <= e; jj += 4) {
        int e0 = col[jj], e1 = col[jj + 1], e2 = col[jj + 2], e3 = col[jj + 3];
        float4 v0 = __ldg(&g_me[e0 * F4 + lane]);
        float4 v1 = __ldg(&g_me[e1 * F4 + lane]);
        float4 v2 = __ldg(&g_me[e2 * F4 + lane]);
        float4 v3 = __ldg(&g_me[e3 * F4 + lane]);
        f4add(a0, v0); f4add(a1, v1); f4add(a2, v2); f4add(a3, v3);
    }
    for (; jj < e; jj++) {
        int e0 = col[jj];
        f4add(a0, __ldg(&g_me[e0 * F4 + lane]));
    }
    float4 sum;
    sum.x = (a0.x + a1.x) + (a2.x + a3.x);
    sum.y = (a0.y + a1.y) + (a2.y + a3.y);
    sum.z = (a0.z + a1.z) + (a2.z + a3.z);
    sum.w = (a0.w + a1.w) + (a2.w + a3.w);

    float dv = g_dvis[w];
    int idx = w * F4 + lane;
    float th = theta[j];
    float4 xv = __ldg(&x4[idx]);

    float m = (j == 0) ? -dv : -2.f * dv;
    float4 r;
    r.x = fmaf(th, xv.x, m * sum.x);
    r.y = fmaf(th, xv.y, m * sum.y);
    r.z = fmaf(th, xv.z, m * sum.z);
    r.w = fmaf(th, xv.w, m * sum.w);

    if (j == 0) {
        float4 old = g_buf0[idx];                  // b_2
        r.x -= old.x; r.y -= old.y; r.z -= old.z; r.w -= old.w;
        __nv_bfloat16 h0 = __float2bfloat16(r.x);
        __nv_bfloat16 h1 = __float2bfloat16(r.y);
        __nv_bfloat16 h2 = __float2bfloat16(r.z);
        __nv_bfloat16 h3 = __float2bfloat16(r.w);
        ushort4 hh = make_ushort4(__bfloat16_as_ushort(h0), __bfloat16_as_ushort(h1),
                                  __bfloat16_as_ushort(h2), __bfloat16_as_ushort(h3));
        ushort4 ll = make_ushort4(
            __bfloat16_as_ushort(__float2bfloat16(r.x - __bfloat162float(h0))),
            __bfloat16_as_ushort(__float2bfloat16(r.y - __bfloat162float(h1))),
            __bfloat16_as_ushort(__float2bfloat16(r.z - __bfloat162float(h2))),
            __bfloat16_as_ushort(__float2bfloat16(r.w - __bfloat162float(h3))));
        *(ushort4*)(g_ah + 4 * (size_t)idx) = hh;
        *(ushort4*)(g_al + 4 * (size_t)idx) = ll;
    } else {
        float4* buf = (j & 1) ? g_buf1 : g_buf0;
        if (j != KORD - 1) {
            float4 old = buf[idx];
            r.x -= old.x; r.y -= old.y; r.z -= old.z; r.w -= old.w;
        }
        buf[idx] = r;
    }
}

// ---------------- GEMM (mma.sync bf16x3, cp.async pipelined) ----------------
// C = relu(A[N,128] @ W[512,128]^T + b). One CTA per 128-row block (grid=391).
// A hi/lo staged ONCE via cp.async; B tiles (128 cols) double-buffered, prefetch
// of tile ct+1 overlaps compute of tile ct. 8 warps as 4m x 2n; warp tile 32x64.
// D(fp32) = Ah*Wh + Ah*Wl + Al*Wh (Al*Wl dropped, ~2^-18 relative).
__global__ void __launch_bounds__(256) k_mma(const float* __restrict__ bias,
                                             float* __restrict__ C) {
    extern __shared__ unsigned sm[];
    unsigned* Ahs = sm;                              // GM*STRW words
    unsigned* Als = Ahs + GM * STRW;
    unsigned* Bbuf = Als + GM * STRW;                // 2 buffers x (Bh + Bl), each GNT*STRW
    int tid = threadIdx.x;
    int row0 = blockIdx.x * GM;
    unsigned smb = (unsigned)__cvta_generic_to_shared(sm);

    // --- stage A (hi/lo) via cp.async, 16B chunks, zero-fill OOB rows ---
    {
        const char* Ah8 = (const char*)g_ah;
        const char* Al8 = (const char*)g_al;
        for (int i = tid; i < GM * 16; i += 256) {
            int r = i >> 4, c4 = i & 15;             // 16 chunks of 16B per 256B row
            int gr = row0 + r;
            unsigned sz = (gr < NN) ? 16u : 0u;
            size_t gofs = (size_t)gr * 256 + c4 * 16;
            unsigned dofs = (unsigned)((r * STRW + c4 * 4) * 4);
            cp_async16(smb + ((unsigned)((char*)Ahs - (char*)sm)) + dofs, Ah8 + gofs, sz);
            cp_async16(smb + ((unsigned)((char*)Als - (char*)sm)) + dofs, Al8 + gofs, sz);
        }
    }
    // --- prefetch B tile 0 into buffer 0 (same commit group as A) ---
    const char* Wh8 = (const char*)g_wh;
    const char* Wl8 = (const char*)g_wl;
    unsigned bbase = (unsigned)((char*)Bbuf - (char*)sm);
    {
        for (int i = tid; i < GNT * 16; i += 256) {
            int r = i >> 4, c4 = i & 15;
            size_t gofs = (size_t)r * 256 + c4 * 16;   // tile 0: col0 = 0
            unsigned dofs = (unsigned)((r * STRW + c4 * 4) * 4);
            cp_async16(smb + bbase + dofs, Wh8 + gofs, 16u);
            cp_async16(smb + bbase + (unsigned)(GNT * STRW * 4) + dofs, Wl8 + gofs, 16u);
        }
    }
    CP_COMMIT();

    int wid = tid >> 5, lane = tid & 31;
    int wm = wid & 3, wn = wid >> 2;       // warp grid 4 (m) x 2 (n)
    int lr = lane >> 2, lc = lane & 3;     // m16n8k16 lane decomposition

    for (int ct = 0; ct < HIDN / GNT; ct++) {
        CP_WAIT0();
        __syncthreads();                   // tile ct data visible; compute ct-1 finished everywhere

        // prefetch tile ct+1 into the alternate buffer, overlapped with compute of ct
        if (ct + 1 < HIDN / GNT) {
            unsigned bo = bbase + (unsigned)(((ct + 1) & 1) * 2 * GNT * STRW * 4);
            size_t colbase = (size_t)(ct + 1) * GNT * 256;
            for (int i = tid; i < GNT * 16; i += 256) {
                int r = i >> 4, c4 = i & 15;
                size_t gofs = colbase + (size_t)r * 256 + c4 * 16;
                unsigned dofs = (unsigned)((r * STRW + c4 * 4) * 4);
                cp_async16(smb + bo + dofs, Wh8 + gofs, 16u);
                cp_async16(smb + bo + (unsigned)(GNT * STRW * 4) + dofs, Wl8 + gofs, 16u);
            }
            CP_COMMIT();
        }

        const unsigned* Bhs = Bbuf + (ct & 1) * 2 * GNT * STRW;
        const unsigned* Bls = Bhs + GNT * STRW;
        int col0 = ct * GNT;

        float acc[2][8][4];
        #pragma unroll
        for (int mf = 0; mf < 2; mf++)
            #pragma unroll
            for (int nf = 0; nf < 8; nf++)
                #pragma unroll
                for (int q = 0; q < 4; q++) acc[mf][nf][q] = 0.f;

        const unsigned* Aps[3] = { Ahs, Ahs, Als };
        const unsigned* Bps[3] = { Bhs, Bls, Bhs };
        #pragma unroll
        for (int ps = 0; ps < 3; ps++) {
            const unsigned* At = Aps[ps];
            const unsigned* Bt = Bps[ps];
            #pragma unroll
            for (int kk = 0; kk < 8; kk++) {   // 8 k-chunks of 16 bf16 (8 words)
                unsigned afr[2][4];
                #pragma unroll
                for (int mf = 0; mf < 2; mf++) {
                    const unsigned* p = At + (wm * 32 + mf * 16 + lr) * STRW + kk * 8 + lc;
                    afr[mf][0] = p[0];
                    afr[mf][1] = p[8 * STRW];
                    afr[mf][2] = p[4];
                    afr[mf][3] = p[8 * STRW + 4];
                }
                #pragma unroll
                for (int nf = 0; nf < 8; nf++) {
                    unsigned bfr[2];
                    const unsigned* p = Bt + (wn * 64 + nf * 8 + lr) * STRW + kk * 8 + lc;
                    bfr[0] = p[0];
                    bfr[1] = p[4];
                    mma_bf16(acc[0][nf], afr[0], bfr);
                    mma_bf16(acc[1][nf], afr[1], bfr);
                }
            }
        }

        // epilogue for this column tile: bias + relu, float2 stores
        #pragma unroll
        for (int mf = 0; mf < 2; mf++) {
            #pragma unroll
            for (int nf = 0; nf < 8; nf++) {
                int r = row0 + wm * 32 + mf * 16 + lr;
                int c = col0 + wn * 64 + nf * 8 + lc * 2;
                float2 bb = *(const float2*)&bias[c];
                if (r < NN) {
                    float2 o;
                    o.x = fmaxf(acc[mf][nf][0] + bb.x, 0.f);
                    o.y = fmaxf(acc[mf][nf][1] + bb.y, 0.f);
                    *(float2*)&C[(size_t)r * HIDN + c] = o;
                }
                int r2 = r + 8;
                if (r2 < NN) {
                    float2 o;
                    o.x = fmaxf(acc[mf][nf][2] + bb.x, 0.f);
                    o.y = fmaxf(acc[mf][nf][3] + bb.y, 0.f);
                    *(float2*)&C[(size_t)r2 * HIDN + c] = o;
                }
            }
        }
    }
}

// ---------------- launch ----------------
extern "C" void kernel_launch(void* const* d_in, const int* in_sizes, int n_in,
                              void* d_out, int out_size) {
    const float* x     = (const float*)d_in[0];
    const void*  he    = (const void*)d_in[1];
    const float* ew    = (const float*)d_in[2];
    const float* theta = (const float*)d_in[3];
    const float* w1    = (const float*)d_in[4];
    const float* b1    = (const float*)d_in[5];
    float*       out   = (float*)d_out;

    const int TB = 256;
    k_zero<<<(NN + TB - 1) / TB, TB>>>((const int*)he);
    k_build<<<(NZ + TB - 1) / TB, TB>>>(he);
    k_degs_init<<<(NN * F4 + TB - 1) / TB, TB>>>(ew, (const float4*)x, theta, w1);

    for (int j = KORD - 1; j >= 0; j--) {
        k_edge<<<NE / 2, TB>>>(j);
        k_node<<<(NN * 32 + TB - 1) / TB, TB>>>((const float4*)x, theta, j);
    }

    // SMEM: A (hi+lo) + 2 x B (hi+lo) = (2 + 4) * 128 * STRW words
    const int SMEM_MMA = (2 * GM * STRW + 4 * GNT * STRW) * 4;  // 208896 B
    cudaFuncSetAttribute(k_mma, cudaFuncAttributeMaxDynamicSharedMemorySize, SMEM_MMA);
    k_mma<<<(NN + GM - 1) / GM, 256, SMEM_MMA>>>(b1, out);
}

// round 14
// speedup vs baseline: 1.3030x; 1.0944x over previous
#include <cuda_runtime.h>
#include <cuda_bf16.h>

#define NN 50000     // nodes
#define NE 10000     // edges
#define NZ 800000    // nnz
#define FIN 128
#define F4 32        // float4 per feature row
#define HIDN 512
#define ECAP 192     // max nodes per edge bucket (Poisson(80), P(>192) ~ 1e-25)
#define VCAP 64      // max edges per node bucket (Poisson(16), P(>64) ~ 1e-20)
#define KORD 10      // Chebyshev order (theta has KORD+1 entries)
#define GM 128       // GEMM CTA tile M (rows per CTA)
#define GNT 128      // GEMM column tile (4 tiles cover HIDN=512)
#define STRW 68      // SMEM row stride in 32-bit words (64 data + 4 pad -> conflict-free frags)

// ---------------- static device scratch (no allocation allowed) ----------------
__device__ int   g_flag32 = 0;    // sticky: 1 if hyperedge_index detected as int32
__device__ int   g_cnt_e[NE];
__device__ int   g_cnt_v[NN];
__device__ int   g_ecol[NE * ECAP];   // node indices, bucketed by edge (7.7 MB)
__device__ int   g_vcol[NN * VCAP];   // edge indices, bucketed by node (12.8 MB)
__device__ float g_dvis[NN];
__device__ float g_dew[NE];
__device__ float4 g_me[NE * F4];      // 5.1 MB
__device__ float4 g_buf0[NN * F4];    // 25.6 MB  (Clenshaw b_j, even parity)
__device__ float4 g_buf1[NN * F4];    // 25.6 MB  (Clenshaw b_j, odd parity)
__device__ __nv_bfloat16 g_ah[NN * FIN];     // 12.8 MB  Clenshaw result, bf16 hi
__device__ __nv_bfloat16 g_al[NN * FIN];     // 12.8 MB  Clenshaw result, bf16 lo
__device__ __nv_bfloat16 g_wh[HIDN * FIN];   // W hi
__device__ __nv_bfloat16 g_wl[HIDN * FIN];   // W lo

// ---------------- generic helpers ----------------
__device__ __forceinline__ float4 f4z() { return make_float4(0.f, 0.f, 0.f, 0.f); }
__device__ __forceinline__ void f4fma(float4& a, float s, const float4& v) {
    a.x = fmaf(s, v.x, a.x); a.y = fmaf(s, v.y, a.y);
    a.z = fmaf(s, v.z, a.z); a.w = fmaf(s, v.w, a.w);
}
__device__ __forceinline__ void f4add(float4& a, const float4& v) {
    a.x += v.x; a.y += v.y; a.z += v.z; a.w += v.w;
}
__device__ __forceinline__ int clampi(int v, int lo, int hi) {
    return min(max(v, lo), hi);
}
__device__ __forceinline__ void get_pair(const void* he, int i, int& node, int& edge) {
    if (g_flag32 == 0) { // int64
        node = (int)((const long long*)he)[i];
        edge = (int)((const long long*)he)[NZ + i];
    } else {             // int32
        node = ((const int*)he)[i];
        edge = ((const int*)he)[NZ + i];
    }
    node = clampi(node, 0, NN - 1);
    edge = clampi(edge, 0, NE - 1);
}

// mma.sync bf16 (baseline PTX, works on plain sm_103 target)
__device__ __forceinline__ void mma_bf16(float* d, const unsigned* a, const unsigned* b) {
    asm volatile(
        "mma.sync.aligned.m16n8k16.row.col.f32.bf16.bf16.f32 "
        "{%0,%1,%2,%3}, {%4,%5,%6,%7}, {%8,%9}, {%0,%1,%2,%3};"
        : "+f"(d[0]), "+f"(d[1]), "+f"(d[2]), "+f"(d[3])
        : "r"(a[0]), "r"(a[1]), "r"(a[2]), "r"(a[3]), "r"(b[0]), "r"(b[1]));
}

// cp.async 16B with zero-fill when sz==0 (baseline PTX, sm_80+)
__device__ __forceinline__ void cp_async16(unsigned dst, const void* src, unsigned sz) {
    asm volatile("cp.async.cg.shared.global [%0], [%1], 16, %2;"
                 :: "r"(dst), "l"(src), "r"(sz) : "memory");
}
#define CP_COMMIT() asm volatile("cp.async.commit_group;" ::: "memory")
#define CP_WAIT0()  asm volatile("cp.async.wait_group 0;" ::: "memory")

// ---------------- launch 0: zero counters + dtype detection ----------------
__global__ void k_zero(const int* __restrict__ he32) {
    int i = blockIdx.x * blockDim.x + threadIdx.x;
    if (i < 4096) {
        if (he32[2 * i + 1] != 0) atomicOr(&g_flag32, 1);
    }
    if (i < NE) g_cnt_e[i] = 0;
    if (i < NN) g_cnt_v[i] = 0;
}

// ---------------- launch 1: single-pass bucketed CSR build (no float atomics) ----------------
__global__ void k_build(const void* __restrict__ he) {
    int i = blockIdx.x * blockDim.x + threadIdx.x;
    if (i >= NZ) return;
    int node, edge;
    get_pair(he, i, node, edge);
    int p = atomicAdd(&g_cnt_e[edge], 1);
    if (p < ECAP) g_ecol[edge * ECAP + p] = node;
    int q = atomicAdd(&g_cnt_v[node], 1);
    if (q < VCAP) g_vcol[node * VCAP + q] = edge;
}

// ---------------- launch 2: norm factors (dvis from buckets) + Clenshaw init + W split ----------------
__global__ void k_degs_init(const float* __restrict__ ew, const float4* __restrict__ x4,
                            const float* __restrict__ theta, const float* __restrict__ W) {
    int i = blockIdx.x * blockDim.x + threadIdx.x;
    if (i < NE) {
        float de = (float)g_cnt_e[i];
        g_dew[i] = (de > 0.f) ? (ew[i] / fmaxf(de, 1e-12f)) : 0.f;
    }
    if (i < NN) {
        // d_v = sum of ew over this node's incident edges, gathered from buckets (no atomics)
        int cnt = min(g_cnt_v[i], VCAP);
        const int* __restrict__ col = g_vcol + i * VCAP;
        float dv = 0.f;
        for (int q = 0; q < cnt; q++) dv += __ldg(&ew[col[q]]);
        g_dvis[i] = (dv > 0.f) ? rsqrtf(fmaxf(dv, 1e-12f)) : 0.f;
    }
    if (i < HIDN * FIN) {
        float v = W[i];
        __nv_bfloat16 h = __float2bfloat16(v);
        g_wh[i] = h;
        g_wl[i] = __float2bfloat16(v - __bfloat162float(h));
    }
    if (i < NN * F4) {
        float th = theta[KORD];
        float4 v = x4[i];
        v.x *= th; v.y *= th; v.z *= th; v.w *= th;
        g_buf0[i] = v;   // b_10 -> buf[10&1] = buf0
    }
}

// ---------------- hot loop: edge aggregation (phase A), 4 warps per edge ----------------
// 2 accumulators (FMA lat=4 covered), 4 loads in flight (MLP preserved), <=32 regs target.
__global__ void __launch_bounds__(256, 8) k_edge(int j) {
    const float4* __restrict__ t = ((j + 1) & 1) ? g_buf1 : g_buf0;
    __shared__ float4 part[8][32];
    int tid = threadIdx.x;
    int wid = tid >> 5;
    int lane = tid & 31;
    int sub = wid >> 2;
    int chunk = wid & 3;
    int e_idx = blockIdx.x * 2 + sub;

    const int* __restrict__ col = g_ecol + e_idx * ECAP;
    int deg = min(g_cnt_e[e_idx], ECAP);

    float4 a0 = f4z(), a1 = f4z();
    int jj = chunk;
    for (; jj + 12 < deg; jj += 16) {
        int n0 = col[jj], n1 = col[jj + 4], n2 = col[jj + 8], n3 = col[jj + 12];
        float w0 = g_dvis[n0], w1 = g_dvis[n1], w2 = g_dvis[n2], w3 = g_dvis[n3];
        float4 v0 = __ldg(&t[n0 * F4 + lane]);
        float4 v1 = __ldg(&t[n1 * F4 + lane]);
        float4 v2 = __ldg(&t[n2 * F4 + lane]);
        float4 v3 = __ldg(&t[n3 * F4 + lane]);
        f4fma(a0, w0, v0); f4fma(a1, w1, v1); f4fma(a0, w2, v2); f4fma(a1, w3, v3);
    }
    for (; jj < deg; jj += 4) {
        int n0 = col[jj];
        float w0 = g_dvis[n0];
        float4 v0 = __ldg(&t[n0 * F4 + lane]);
        f4fma(a0, w0, v0);
    }
    float4 a;
    a.x = a0.x + a1.x;
    a.y = a0.y + a1.y;
    a.z = a0.z + a1.z;
    a.w = a0.w + a1.w;
    part[wid][lane] = a;
    __syncthreads();

    if (chunk == 0) {
        int b = sub * 4;
        float4 p0 = part[b][lane], p1 = part[b + 1][lane];
        float4 p2 = part[b + 2][lane], p3 = part[b + 3][lane];
        float dw = g_dew[e_idx];
        float4 o;
        o.x = dw * ((p0.x + p1.x) + (p2.x + p3.x));
        o.y = dw * ((p0.y + p1.y) + (p2.y + p3.y));
        o.z = dw * ((p0.z + p1.z) + (p2.z + p3.z));
        o.w = dw * ((p0.w + p1.w) + (p2.w + p3.w));
        g_me[e_idx * F4 + lane] = o;
    }
}

// ---------------- hot loop: node aggregation + Clenshaw step (phase B) ----------------
// j>=1: b_j = theta[j]*x - 2*dvis*sum - b_{j+2}  (in-place in buf[j&1])
// j==0: out = theta[0]*x - dvis*sum - b_2, split to bf16 hi/lo for the GEMM
__global__ void __launch_bounds__(256, 8) k_node(const float4* __restrict__ x4,
                                                 const float* __restrict__ theta, int j) {
    int w = (blockIdx.x * blockDim.x + threadIdx.x) >> 5;
    int lane = threadIdx.x & 31;
    if (w >= NN) return;
    const int* __restrict__ col = g_vcol + w * VCAP;
    int e = min(g_cnt_v[w], VCAP);
    float4 a0 = f4z(), a1 = f4z();
    int jj = 0;
    for (; jj + 4 <= e; jj += 4) {
        int e0 = col[jj], e1 = col[jj + 1], e2 = col[jj + 2], e3 = col[jj + 3];
        float4 v0 = __ldg(&g_me[e0 * F4 + lane]);
        float4 v1 = __ldg(&g_me[e1 * F4 + lane]);
        float4 v2 = __ldg(&g_me[e2 * F4 + lane]);
        float4 v3 = __ldg(&g_me[e3 * F4 + lane]);
        f4add(a0, v0); f4add(a1, v1); f4add(a0, v2); f4add(a1, v3);
    }
    for (; jj < e; jj++) {
        int e0 = col[jj];
        f4add(a0, __ldg(&g_me[e0 * F4 + lane]));
    }
    float4 sum;
    sum.x = a0.x + a1.x;
    sum.y = a0.y + a1.y;
    sum.z = a0.z + a1.z;
    sum.w = a0.w + a1.w;

    float dv = g_dvis[w];
    int idx = w * F4 + lane;
    float th = theta[j];
    float4 xv = __ldg(&x4[idx]);

    float m = (j == 0) ? -dv : -2.f * dv;
    float4 r;
    r.x = fmaf(th, xv.x, m * sum.x);
    r.y = fmaf(th, xv.y, m * sum.y);
    r.z = fmaf(th, xv.z, m * sum.z);
    r.w = fmaf(th, xv.w, m * sum.w);

    if (j == 0) {
        float4 old = g_buf0[idx];                  // b_2
        r.x -= old.x; r.y -= old.y; r.z -= old.z; r.w -= old.w;
        __nv_bfloat16 h0 = __float2bfloat16(r.x);
        __nv_bfloat16 h1 = __float2bfloat16(r.y);
        __nv_bfloat16 h2 = __float2bfloat16(r.z);
        __nv_bfloat16 h3 = __float2bfloat16(r.w);
        ushort4 hh = make_ushort4(__bfloat16_as_ushort(h0), __bfloat16_as_ushort(h1),
                                  __bfloat16_as_ushort(h2), __bfloat16_as_ushort(h3));
        ushort4 ll = make_ushort4(
            __bfloat16_as_ushort(__float2bfloat16(r.x - __bfloat162float(h0))),
            __bfloat16_as_ushort(__float2bfloat16(r.y - __bfloat162float(h1))),
            __bfloat16_as_ushort(__float2bfloat16(r.z - __bfloat162float(h2))),
            __bfloat16_as_ushort(__float2bfloat16(r.w - __bfloat162float(h3))));
        *(ushort4*)(g_ah + 4 * (size_t)idx) = hh;
        *(ushort4*)(g_al + 4 * (size_t)idx) = ll;
    } else {
        float4* buf = (j & 1) ? g_buf1 : g_buf0;
        if (j != KORD - 1) {
            float4 old = buf[idx];
            r.x -= old.x; r.y -= old.y; r.z -= old.z; r.w -= old.w;
        }
        buf[idx] = r;
    }
}

// ---------------- GEMM (mma.sync bf16x3, cp.async pipelined) ----------------
// C = relu(A[N,128] @ W[512,128]^T + b). One CTA per 128-row block (grid=391).
// A hi/lo staged ONCE via cp.async; B tiles (128 cols) double-buffered, prefetch
// of tile ct+1 overlaps compute of tile ct. 8 warps as 4m x 2n; warp tile 32x64.
// D(fp32) = Ah*Wh + Ah*Wl + Al*Wh (Al*Wl dropped, ~2^-18 relative).
__global__ void __launch_bounds__(256) k_mma(const float* __restrict__ bias,
                                             float* __restrict__ C) {
    extern __shared__ unsigned sm[];
    unsigned* Ahs = sm;                              // GM*STRW words
    unsigned* Als = Ahs + GM * STRW;
    unsigned* Bbuf = Als + GM * STRW;                // 2 buffers x (Bh + Bl), each GNT*STRW
    int tid = threadIdx.x;
    int row0 = blockIdx.x * GM;
    unsigned smb = (unsigned)__cvta_generic_to_shared(sm);

    // --- stage A (hi/lo) via cp.async, 16B chunks, zero-fill OOB rows ---
    {
        const char* Ah8 = (const char*)g_ah;
        const char* Al8 = (const char*)g_al;
        for (int i = tid; i < GM * 16; i += 256) {
            int r = i >> 4, c4 = i & 15;             // 16 chunks of 16B per 256B row
            int gr = row0 + r;
            unsigned sz = (gr < NN) ? 16u : 0u;
            size_t gofs = (size_t)gr * 256 + c4 * 16;
            unsigned dofs = (unsigned)((r * STRW + c4 * 4) * 4);
            cp_async16(smb + ((unsigned)((char*)Ahs - (char*)sm)) + dofs, Ah8 + gofs, sz);
            cp_async16(smb + ((unsigned)((char*)Als - (char*)sm)) + dofs, Al8 + gofs, sz);
        }
    }
    // --- prefetch B tile 0 into buffer 0 (same commit group as A) ---
    const char* Wh8 = (const char*)g_wh;
    const char* Wl8 = (const char*)g_wl;
    unsigned bbase = (unsigned)((char*)Bbuf - (char*)sm);
    {
        for (int i = tid; i < GNT * 16; i += 256) {
            int r = i >> 4, c4 = i & 15;
            size_t gofs = (size_t)r * 256 + c4 * 16;   // tile 0: col0 = 0
            unsigned dofs = (unsigned)((r * STRW + c4 * 4) * 4);
            cp_async16(smb + bbase + dofs, Wh8 + gofs, 16u);
            cp_async16(smb + bbase + (unsigned)(GNT * STRW * 4) + dofs, Wl8 + gofs, 16u);
        }
    }
    CP_COMMIT();

    int wid = tid >> 5, lane = tid & 31;
    int wm = wid & 3, wn = wid >> 2;       // warp grid 4 (m) x 2 (n)
    int lr = lane >> 2, lc = lane & 3;     // m16n8k16 lane decomposition

    for (int ct = 0; ct < HIDN / GNT; ct++) {
        CP_WAIT0();
        __syncthreads();                   // tile ct data visible; compute ct-1 finished everywhere

        // prefetch tile ct+1 into the alternate buffer, overlapped with compute of ct
        if (ct + 1 < HIDN / GNT) {
            unsigned bo = bbase + (unsigned)(((ct + 1) & 1) * 2 * GNT * STRW * 4);
            size_t colbase = (size_t)(ct + 1) * GNT * 256;
            for (int i = tid; i < GNT * 16; i += 256) {
                int r = i >> 4, c4 = i & 15;
                size_t gofs = colbase + (size_t)r * 256 + c4 * 16;
                unsigned dofs = (unsigned)((r * STRW + c4 * 4) * 4);
                cp_async16(smb + bo + dofs, Wh8 + gofs, 16u);
                cp_async16(smb + bo + (unsigned)(GNT * STRW * 4) + dofs, Wl8 + gofs, 16u);
            }
            CP_COMMIT();
        }

        const unsigned* Bhs = Bbuf + (ct & 1) * 2 * GNT * STRW;
        const unsigned* Bls = Bhs + GNT * STRW;
        int col0 = ct * GNT;

        float acc[2][8][4];
        #pragma unroll
        for (int mf = 0; mf < 2; mf++)
            #pragma unroll
            for (int nf = 0; nf < 8; nf++)
                #pragma unroll
                for (int q = 0; q < 4; q++) acc[mf][nf][q] = 0.f;

        const unsigned* Aps[3] = { Ahs, Ahs, Als };
        const unsigned* Bps[3] = { Bhs, Bls, Bhs };
        #pragma unroll
        for (int ps = 0; ps < 3; ps++) {
            const unsigned* At = Aps[ps];
            const unsigned* Bt = Bps[ps];
            #pragma unroll
            for (int kk = 0; kk < 8; kk++) {   // 8 k-chunks of 16 bf16 (8 words)
                unsigned afr[2][4];
                #pragma unroll
                for (int mf = 0; mf < 2; mf++) {
                    const unsigned* p = At + (wm * 32 + mf * 16 + lr) * STRW + kk * 8 + lc;
                    afr[mf][0] = p[0];
                    afr[mf][1] = p[8 * STRW];
                    afr[mf][2] = p[4];
                    afr[mf][3] = p[8 * STRW + 4];
                }
                #pragma unroll
                for (int nf = 0; nf < 8; nf++) {
                    unsigned bfr[2];
                    const unsigned* p = Bt + (wn * 64 + nf * 8 + lr) * STRW + kk * 8 + lc;
                    bfr[0] = p[0];
                    bfr[1] = p[4];
                    mma_bf16(acc[0][nf], afr[0], bfr);
                    mma_bf16(acc[1][nf], afr[1], bfr);
                }
            }
        }

        // epilogue for this column tile: bias + relu, float2 stores
        #pragma unroll
        for (int mf = 0; mf < 2; mf++) {
            #pragma unroll
            for (int nf = 0; nf < 8; nf++) {
                int r = row0 + wm * 32 + mf * 16 + lr;
                int c = col0 + wn * 64 + nf * 8 + lc * 2;
                float2 bb = *(const float2*)&bias[c];
                if (r < NN) {
                    float2 o;
                    o.x = fmaxf(acc[mf][nf][0] + bb.x, 0.f);
                    o.y = fmaxf(acc[mf][nf][1] + bb.y, 0.f);
                    *(float2*)&C[(size_t)r * HIDN + c] = o;
                }
                int r2 = r + 8;
                if (r2 < NN) {
                    float2 o;
                    o.x = fmaxf(acc[mf][nf][2] + bb.x, 0.f);
                    o.y = fmaxf(acc[mf][nf][3] + bb.y, 0.f);
                    *(float2*)&C[(size_t)r2 * HIDN + c] = o;
                }
            }
        }
    }
}

// ---------------- launch ----------------
extern "C" void kernel_launch(void* const* d_in, const int* in_sizes, int n_in,
                              void* d_out, int out_size) {
    const float* x     = (const float*)d_in[0];
    const void*  he    = (const void*)d_in[1];
    const float* ew    = (const float*)d_in[2];
    const float* theta = (const float*)d_in[3];
    const float* w1    = (const float*)d_in[4];
    const float* b1    = (const float*)d_in[5];
    float*       out   = (float*)d_out;

    const int TB = 256;
    k_zero<<<(NN + TB - 1) / TB, TB>>>((const int*)he);
    k_build<<<(NZ + TB - 1) / TB, TB>>>(he);
    k_degs_init<<<(NN * F4 + TB - 1) / TB, TB>>>(ew, (const float4*)x, theta, w1);

    for (int j = KORD - 1; j >= 0; j--) {
        k_edge<<<NE / 2, TB>>>(j);
        k_node<<<(NN * 32 + TB - 1) / TB, TB>>>((const float4*)x, theta, j);
    }

    // SMEM: A (hi+lo) + 2 x B (hi+lo) = (2 + 4) * 128 * STRW words
    const int SMEM_MMA = (2 * GM * STRW + 4 * GNT * STRW) * 4;  // 208896 B
    cudaFuncSetAttribute(k_mma, cudaFuncAttributeMaxDynamicSharedMemorySize, SMEM_MMA);
    k_mma<<<(NN + GM - 1) / GM, 256, SMEM_MMA>>>(b1, out);
}

// round 15
// speedup vs baseline: 1.3787x; 1.0581x over previous
#include <cuda_runtime.h>
#include <cuda_bf16.h>

#define NN 50000     // nodes
#define NE 10000     // edges
#define NZ 800000    // nnz
#define FIN 128
#define F4 32        // float4 per feature row
#define HIDN 512
#define ECAP 192     // max nodes per edge bucket (Poisson(80), P(>192) ~ 1e-25)
#define VCAP 64      // max edges per node bucket (Poisson(16), P(>64) ~ 1e-20)
#define KORD 10      // Chebyshev order (theta has KORD+1 entries)
#define GM 128       // GEMM CTA tile M (rows per CTA)
#define GNT 128      // GEMM column tile (4 tiles cover HIDN=512)
#define STRW 68      // SMEM row stride in 32-bit words (64 data + 4 pad -> conflict-free frags)

// ---------------- static device scratch (no allocation allowed) ----------------
__device__ int   g_flag32 = 0;    // sticky: 1 if hyperedge_index detected as int32
__device__ int   g_cnt_e[NE];
__device__ int   g_cnt_v[NN];
__device__ int   g_ecol[NE * ECAP];   // node indices, bucketed by edge (7.7 MB)
__device__ int   g_vcol[NN * VCAP];   // edge indices, bucketed by node (12.8 MB)
__device__ float g_dvis[NN];
__device__ float g_dew[NE];
__device__ float4 g_me[NE * F4];      // 5.1 MB
__device__ float4 g_buf0[NN * F4];    // 25.6 MB  (scaled Clenshaw c_j, even parity)
__device__ float4 g_buf1[NN * F4];    // 25.6 MB  (scaled Clenshaw c_j, odd parity)
__device__ __nv_bfloat16 g_ah[NN * FIN];     // 12.8 MB  Clenshaw result, bf16 hi
__device__ __nv_bfloat16 g_al[NN * FIN];     // 12.8 MB  Clenshaw result, bf16 lo
__device__ __nv_bfloat16 g_wh[HIDN * FIN];   // W hi
__device__ __nv_bfloat16 g_wl[HIDN * FIN];   // W lo

// ---------------- generic helpers ----------------
__device__ __forceinline__ float4 f4z() { return make_float4(0.f, 0.f, 0.f, 0.f); }
__device__ __forceinline__ void f4add(float4& a, const float4& v) {
    a.x += v.x; a.y += v.y; a.z += v.z; a.w += v.w;
}
__device__ __forceinline__ int clampi(int v, int lo, int hi) {
    return min(max(v, lo), hi);
}
__device__ __forceinline__ void get_pair(const void* he, int i, int& node, int& edge) {
    if (g_flag32 == 0) { // int64
        node = (int)((const long long*)he)[i];
        edge = (int)((const long long*)he)[NZ + i];
    } else {             // int32
        node = ((const int*)he)[i];
        edge = ((const int*)he)[NZ + i];
    }
    node = clampi(node, 0, NN - 1);
    edge = clampi(edge, 0, NE - 1);
}

// mma.sync bf16 (baseline PTX, works on plain sm_103 target)
__device__ __forceinline__ void mma_bf16(float* d, const unsigned* a, const unsigned* b) {
    asm volatile(
        "mma.sync.aligned.m16n8k16.row.col.f32.bf16.bf16.f32 "
        "{%0,%1,%2,%3}, {%4,%5,%6,%7}, {%8,%9}, {%0,%1,%2,%3};"
        : "+f"(d[0]), "+f"(d[1]), "+f"(d[2]), "+f"(d[3])
        : "r"(a[0]), "r"(a[1]), "r"(a[2]), "r"(a[3]), "r"(b[0]), "r"(b[1]));
}

// cp.async 16B with zero-fill when sz==0 (baseline PTX, sm_80+)
__device__ __forceinline__ void cp_async16(unsigned dst, const void* src, unsigned sz) {
    asm volatile("cp.async.cg.shared.global [%0], [%1], 16, %2;"
                 :: "r"(dst), "l"(src), "r"(sz) : "memory");
}
#define CP_COMMIT() asm volatile("cp.async.commit_group;" ::: "memory")
#define CP_WAIT0()  asm volatile("cp.async.wait_group 0;" ::: "memory")

// ---------------- launch 0: zero counters + dtype detection ----------------
__global__ void k_zero(const int* __restrict__ he32) {
    int i = blockIdx.x * blockDim.x + threadIdx.x;
    if (i < 4096) {
        if (he32[2 * i + 1] != 0) atomicOr(&g_flag32, 1);
    }
    if (i < NE) g_cnt_e[i] = 0;
    if (i < NN) g_cnt_v[i] = 0;
}

// ---------------- launch 1: single-pass bucketed CSR build ----------------
__global__ void k_build(const void* __restrict__ he) {
    int i = blockIdx.x * blockDim.x + threadIdx.x;
    if (i >= NZ) return;
    int node, edge;
    get_pair(he, i, node, edge);
    int p = atomicAdd(&g_cnt_e[edge], 1);
    if (p < ECAP) g_ecol[edge * ECAP + p] = node;
    int q = atomicAdd(&g_cnt_v[node], 1);
    if (q < VCAP) g_vcol[node * VCAP + q] = edge;
}

// ---------------- launch 2: norm factors (dvis from buckets) + W bf16 split ----------------
__global__ void k_degs(const float* __restrict__ ew, const float* __restrict__ W) {
    int i = blockIdx.x * blockDim.x + threadIdx.x;
    if (i < NE) {
        float de = (float)g_cnt_e[i];
        g_dew[i] = (de > 0.f) ? (ew[i] / fmaxf(de, 1e-12f)) : 0.f;
    }
    if (i < NN) {
        int cnt = min(g_cnt_v[i], VCAP);
        const int* __restrict__ col = g_vcol + i * VCAP;
        float dv = 0.f;
        for (int q = 0; q < cnt; q++) dv += __ldg(&ew[col[q]]);
        g_dvis[i] = (dv > 0.f) ? rsqrtf(fmaxf(dv, 1e-12f)) : 0.f;
    }
    if (i < HIDN * FIN) {
        float v = W[i];
        __nv_bfloat16 h = __float2bfloat16(v);
        g_wh[i] = h;
        g_wl[i] = __float2bfloat16(v - __bfloat162float(h));
    }
}

// ---------------- launch 3: Clenshaw init c_10 = theta[10] * dvis * x -> buf0 ----------------
__global__ void k_initc(const float4* __restrict__ x4, const float* __restrict__ theta) {
    int i = blockIdx.x * blockDim.x + threadIdx.x;
    if (i >= NN * F4) return;
    float a = theta[KORD] * g_dvis[i >> 5];
    float4 v = x4[i];
    v.x *= a; v.y *= a; v.z *= a; v.w *= a;
    g_buf0[i] = v;   // c_10 -> buf[10&1] = buf0
}

// ---------------- hot loop: edge aggregation (phase A), 4 warps per edge ----------------
// Scaled space: m_e[e,:] = de_w[e] * sum_{v in e} c_{j+1}[v,:]  (no dvis gather)
__global__ void __launch_bounds__(256, 8) k_edge(int j) {
    const float4* __restrict__ t = ((j + 1) & 1) ? g_buf1 : g_buf0;
    __shared__ float4 part[8][32];
    int tid = threadIdx.x;
    int wid = tid >> 5;
    int lane = tid & 31;
    int sub = wid >> 2;
    int chunk = wid & 3;
    int e_idx = blockIdx.x * 2 + sub;

    const int* __restrict__ col = g_ecol + e_idx * ECAP;
    int deg = min(g_cnt_e[e_idx], ECAP);

    float4 a0 = f4z(), a1 = f4z();
    int jj = chunk;
    for (; jj + 12 < deg; jj += 16) {
        int n0 = col[jj], n1 = col[jj + 4], n2 = col[jj + 8], n3 = col[jj + 12];
        float4 v0 = __ldg(&t[n0 * F4 + lane]);
        float4 v1 = __ldg(&t[n1 * F4 + lane]);
        float4 v2 = __ldg(&t[n2 * F4 + lane]);
        float4 v3 = __ldg(&t[n3 * F4 + lane]);
        f4add(a0, v0); f4add(a1, v1); f4add(a0, v2); f4add(a1, v3);
    }
    for (; jj < deg; jj += 4) {
        int n0 = col[jj];
        float4 v0 = __ldg(&t[n0 * F4 + lane]);
        f4add(a0, v0);
    }
    float4 a;
    a.x = a0.x + a1.x;
    a.y = a0.y + a1.y;
    a.z = a0.z + a1.z;
    a.w = a0.w + a1.w;
    part[wid][lane] = a;
    __syncthreads();

    if (chunk == 0) {
        int b = sub * 4;
        float4 p0 = part[b][lane], p1 = part[b + 1][lane];
        float4 p2 = part[b + 2][lane], p3 = part[b + 3][lane];
        float dw = g_dew[e_idx];
        float4 o;
        o.x = dw * ((p0.x + p1.x) + (p2.x + p3.x));
        o.y = dw * ((p0.y + p1.y) + (p2.y + p3.y));
        o.z = dw * ((p0.z + p1.z) + (p2.z + p3.z));
        o.w = dw * ((p0.w + p1.w) + (p2.w + p3.w));
        g_me[e_idx * F4 + lane] = o;
    }
}

// ---------------- hot loop: node aggregation + scaled Clenshaw step (phase B) ----------------
// j>=1: c_j = (theta_j*s)*x - (2*s^2)*sum - c_{j+2}   (in-place in buf[j&1])
// j==0: out = theta_0*x - s*sum - b_2, b_2 = (s>0 ? c_2/s : beta2*x); split to bf16 hi/lo
__global__ void __launch_bounds__(256, 8) k_node(const float4* __restrict__ x4,
                                                 const float* __restrict__ theta, int j) {
    int w = (blockIdx.x * blockDim.x + threadIdx.x) >> 5;
    int lane = threadIdx.x & 31;
    if (w >= NN) return;
    const int* __restrict__ col = g_vcol + w * VCAP;
    int e = min(g_cnt_v[w], VCAP);
    float4 a0 = f4z(), a1 = f4z();
    int jj = 0;
    for (; jj + 4 <= e; jj += 4) {
        int e0 = col[jj], e1 = col[jj + 1], e2 = col[jj + 2], e3 = col[jj + 3];
        float4 v0 = __ldg(&g_me[e0 * F4 + lane]);
        float4 v1 = __ldg(&g_me[e1 * F4 + lane]);
        float4 v2 = __ldg(&g_me[e2 * F4 + lane]);
        float4 v3 = __ldg(&g_me[e3 * F4 + lane]);
        f4add(a0, v0); f4add(a1, v1); f4add(a0, v2); f4add(a1, v3);
    }
    for (; jj < e; jj++) {
        int e0 = col[jj];
        f4add(a0, __ldg(&g_me[e0 * F4 + lane]));
    }
    float4 sum;
    sum.x = a0.x + a1.x;
    sum.y = a0.y + a1.y;
    sum.z = a0.z + a1.z;
    sum.w = a0.w + a1.w;

    float s = g_dvis[w];
    int idx = w * F4 + lane;
    float4 xv = __ldg(&x4[idx]);

    if (j == 0) {
        // out = theta0*x - s*sum - b_2
        float4 c2 = g_buf0[idx];
        float th0 = theta[0];
        float4 b2;
        if (s > 0.f) {
            float inv = 1.f / s;
            b2.x = c2.x * inv; b2.y = c2.y * inv; b2.z = c2.z * inv; b2.w = c2.w * inv;
        } else {
            float beta2 = theta[2] - theta[4] + theta[6] - theta[8] + theta[10];
            b2.x = beta2 * xv.x; b2.y = beta2 * xv.y; b2.z = beta2 * xv.z; b2.w = beta2 * xv.w;
        }
        float ms = -s;
        float4 r;
        r.x = fmaf(th0, xv.x, ms * sum.x) - b2.x;
        r.y = fmaf(th0, xv.y, ms * sum.y) - b2.y;
        r.z = fmaf(th0, xv.z, ms * sum.z) - b2.z;
        r.w = fmaf(th0, xv.w, ms * sum.w) - b2.w;
        __nv_bfloat16 h0 = __float2bfloat16(r.x);
        __nv_bfloat16 h1 = __float2bfloat16(r.y);
        __nv_bfloat16 h2 = __float2bfloat16(r.z);
        __nv_bfloat16 h3 = __float2bfloat16(r.w);
        ushort4 hh = make_ushort4(__bfloat16_as_ushort(h0), __bfloat16_as_ushort(h1),
                                  __bfloat16_as_ushort(h2), __bfloat16_as_ushort(h3));
        ushort4 ll = make_ushort4(
            __bfloat16_as_ushort(__float2bfloat16(r.x - __bfloat162float(h0))),
            __bfloat16_as_ushort(__float2bfloat16(r.y - __bfloat162float(h1))),
            __bfloat16_as_ushort(__float2bfloat16(r.z - __bfloat162float(h2))),
            __bfloat16_as_ushort(__float2bfloat16(r.w - __bfloat162float(h3))));
        *(ushort4*)(g_ah + 4 * (size_t)idx) = hh;
        *(ushort4*)(g_al + 4 * (size_t)idx) = ll;
    } else {
        float a = theta[j] * s;
        float m = -2.f * s * s;
        float4 r;
        r.x = fmaf(a, xv.x, m * sum.x);
        r.y = fmaf(a, xv.y, m * sum.y);
        r.z = fmaf(a, xv.z, m * sum.z);
        r.w = fmaf(a, xv.w, m * sum.w);
        float4* buf = (j & 1) ? g_buf1 : g_buf0;
        if (j != KORD - 1) {
            float4 old = buf[idx];
            r.x -= old.x; r.y -= old.y; r.z -= old.z; r.w -= old.w;
        }
        buf[idx] = r;
    }
}

// ---------------- GEMM (mma.sync bf16x3, cp.async pipelined) ----------------
// C = relu(A[N,128] @ W[512,128]^T + b). One CTA per 128-row block (grid=391).
// A hi/lo staged ONCE via cp.async; B tiles (128 cols) double-buffered, prefetch
// of tile ct+1 overlaps compute of tile ct. 8 warps as 4m x 2n; warp tile 32x64.
// D(fp32) = Ah*Wh + Ah*Wl + Al*Wh (Al*Wl dropped, ~2^-18 relative).
__global__ void __launch_bounds__(256) k_mma(const float* __restrict__ bias,
                                             float* __restrict__ C) {
    extern __shared__ unsigned sm[];
    unsigned* Ahs = sm;                              // GM*STRW words
    unsigned* Als = Ahs + GM * STRW;
    unsigned* Bbuf = Als + GM * STRW;                // 2 buffers x (Bh + Bl), each GNT*STRW
    int tid = threadIdx.x;
    int row0 = blockIdx.x * GM;
    unsigned smb = (unsigned)__cvta_generic_to_shared(sm);

    // --- stage A (hi/lo) via cp.async, 16B chunks, zero-fill OOB rows ---
    {
        const char* Ah8 = (const char*)g_ah;
        const char* Al8 = (const char*)g_al;
        for (int i = tid; i < GM * 16; i += 256) {
            int r = i >> 4, c4 = i & 15;             // 16 chunks of 16B per 256B row
            int gr = row0 + r;
            unsigned sz = (gr < NN) ? 16u : 0u;
            size_t gofs = (size_t)gr * 256 + c4 * 16;
            unsigned dofs = (unsigned)((r * STRW + c4 * 4) * 4);
            cp_async16(smb + ((unsigned)((char*)Ahs - (char*)sm)) + dofs, Ah8 + gofs, sz);
            cp_async16(smb + ((unsigned)((char*)Als - (char*)sm)) + dofs, Al8 + gofs, sz);
        }
    }
    // --- prefetch B tile 0 into buffer 0 (same commit group as A) ---
    const char* Wh8 = (const char*)g_wh;
    const char* Wl8 = (const char*)g_wl;
    unsigned bbase = (unsigned)((char*)Bbuf - (char*)sm);
    {
        for (int i = tid; i < GNT * 16; i += 256) {
            int r = i >> 4, c4 = i & 15;
            size_t gofs = (size_t)r * 256 + c4 * 16;   // tile 0: col0 = 0
            unsigned dofs = (unsigned)((r * STRW + c4 * 4) * 4);
            cp_async16(smb + bbase + dofs, Wh8 + gofs, 16u);
            cp_async16(smb + bbase + (unsigned)(GNT * STRW * 4) + dofs, Wl8 + gofs, 16u);
        }
    }
    CP_COMMIT();

    int wid = tid >> 5, lane = tid & 31;
    int wm = wid & 3, wn = wid >> 2;       // warp grid 4 (m) x 2 (n)
    int lr = lane >> 2, lc = lane & 3;     // m16n8k16 lane decomposition

    for (int ct = 0; ct < HIDN / GNT; ct++) {
        CP_WAIT0();
        __syncthreads();                   // tile ct data visible; compute ct-1 finished everywhere

        // prefetch tile ct+1 into the alternate buffer, overlapped with compute of ct
        if (ct + 1 < HIDN / GNT) {
            unsigned bo = bbase + (unsigned)(((ct + 1) & 1) * 2 * GNT * STRW * 4);
            size_t colbase = (size_t)(ct + 1) * GNT * 256;
            for (int i = tid; i < GNT * 16; i += 256) {
                int r = i >> 4, c4 = i & 15;
                size_t gofs = colbase + (size_t)r * 256 + c4 * 16;
                unsigned dofs = (unsigned)((r * STRW + c4 * 4) * 4);
                cp_async16(smb + bo + dofs, Wh8 + gofs, 16u);
                cp_async16(smb + bo + (unsigned)(GNT * STRW * 4) + dofs, Wl8 + gofs, 16u);
            }
            CP_COMMIT();
        }

        const unsigned* Bhs = Bbuf + (ct & 1) * 2 * GNT * STRW;
        const unsigned* Bls = Bhs + GNT * STRW;
        int col0 = ct * GNT;

        float acc[2][8][4];
        #pragma unroll
        for (int mf = 0; mf < 2; mf++)
            #pragma unroll
            for (int nf = 0; nf < 8; nf++)
                #pragma unroll
                for (int q = 0; q < 4; q++) acc[mf][nf][q] = 0.f;

        const unsigned* Aps[3] = { Ahs, Ahs, Als };
        const unsigned* Bps[3] = { Bhs, Bls, Bhs };
        #pragma unroll
        for (int ps = 0; ps < 3; ps++) {
            const unsigned* At = Aps[ps];
            const unsigned* Bt = Bps[ps];
            #pragma unroll
            for (int kk = 0; kk < 8; kk++) {   // 8 k-chunks of 16 bf16 (8 words)
                unsigned afr[2][4];
                #pragma unroll
                for (int mf = 0; mf < 2; mf++) {
                    const unsigned* p = At + (wm * 32 + mf * 16 + lr) * STRW + kk * 8 + lc;
                    afr[mf][0] = p[0];
                    afr[mf][1] = p[8 * STRW];
                    afr[mf][2] = p[4];
                    afr[mf][3] = p[8 * STRW + 4];
                }
                #pragma unroll
                for (int nf = 0; nf < 8; nf++) {
                    unsigned bfr[2];
                    const unsigned* p = Bt + (wn * 64 + nf * 8 + lr) * STRW + kk * 8 + lc;
                    bfr[0] = p[0];
                    bfr[1] = p[4];
                    mma_bf16(acc[0][nf], afr[0], bfr);
                    mma_bf16(acc[1][nf], afr[1], bfr);
                }
            }
        }

        // epilogue for this column tile: bias + relu, float2 stores
        #pragma unroll
        for (int mf = 0; mf < 2; mf++) {
            #pragma unroll
            for (int nf = 0; nf < 8; nf++) {
                int r = row0 + wm * 32 + mf * 16 + lr;
                int c = col0 + wn * 64 + nf * 8 + lc * 2;
                float2 bb = *(const float2*)&bias[c];
                if (r < NN) {
                    float2 o;
                    o.x = fmaxf(acc[mf][nf][0] + bb.x, 0.f);
                    o.y = fmaxf(acc[mf][nf][1] + bb.y, 0.f);
                    *(float2*)&C[(size_t)r * HIDN + c] = o;
                }
                int r2 = r + 8;
                if (r2 < NN) {
                    float2 o;
                    o.x = fmaxf(acc[mf][nf][2] + bb.x, 0.f);
                    o.y = fmaxf(acc[mf][nf][3] + bb.y, 0.f);
                    *(float2*)&C[(size_t)r2 * HIDN + c] = o;
                }
            }
        }
    }
}

// ---------------- launch ----------------
extern "C" void kernel_launch(void* const* d_in, const int* in_sizes, int n_in,
                              void* d_out, int out_size) {
    const float* x     = (const float*)d_in[0];
    const void*  he    = (const void*)d_in[1];
    const float* ew    = (const float*)d_in[2];
    const float* theta = (const float*)d_in[3];
    const float* w1    = (const float*)d_in[4];
    const float* b1    = (const float*)d_in[5];
    float*       out   = (float*)d_out;

    const int TB = 256;
    k_zero<<<(NN + TB - 1) / TB, TB>>>((const int*)he);
    k_build<<<(NZ + TB - 1) / TB, TB>>>(he);
    k_degs<<<(HIDN * FIN + TB - 1) / TB, TB>>>(ew, w1);
    k_initc<<<(NN * F4 + TB - 1) / TB, TB>>>((const float4*)x, theta);

    for (int j = KORD - 1; j >= 0; j--) {
        k_edge<<<NE / 2, TB>>>(j);
        k_node<<<(NN * 32 + TB - 1) / TB, TB>>>((const float4*)x, theta, j);
    }

    // SMEM: A (hi+lo) + 2 x B (hi+lo) = (2 + 4) * 128 * STRW words
    const int SMEM_MMA = (2 * GM * STRW + 4 * GNT * STRW) * 4;  // 208896 B
    cudaFuncSetAttribute(k_mma, cudaFuncAttributeMaxDynamicSharedMemorySize, SMEM_MMA);
    k_mma<<<(NN + GM - 1) / GM, 256, SMEM_MMA>>>(b1, out);
}

// round 16
// speedup vs baseline: 1.3969x; 1.0132x over previous
#include <cuda_runtime.h>
#include <cuda_bf16.h>

#define NN 50000     // nodes
#define NE 10000     // edges
#define NZ 800000    // nnz
#define FIN 128
#define F4 32        // float4 per feature row
#define HIDN 512
#define ECAP 192     // max nodes per edge bucket (Poisson(80), P(>192) ~ 1e-25)
#define VCAP 64      // max edges per node bucket (Poisson(16), P(>64) ~ 1e-20)
#define KORD 10      // Chebyshev order (theta has KORD+1 entries)
#define GM 128       // GEMM CTA tile M (rows per CTA)
#define GNT 128      // GEMM column tile (4 tiles cover HIDN=512)
#define STRW 68      // SMEM row stride in 32-bit words (64 data + 4 pad -> conflict-free frags)

// ---------------- static device scratch (no allocation allowed) ----------------
__device__ int   g_flag32 = 0;    // sticky: 1 if hyperedge_index detected as int32
__device__ int   g_cnt_e[NE];
__device__ int   g_cnt_v[NN];
__device__ int   g_ecol[NE * ECAP];   // node indices, bucketed by edge (7.7 MB)
__device__ int   g_vcol[NN * VCAP];   // edge indices, bucketed by node (12.8 MB)
__device__ float g_dvis[NN];
__device__ float g_dew[NE];
__device__ float4 g_me[NE * F4];      // 5.1 MB
__device__ float4 g_buf0[NN * F4];    // 25.6 MB  (scaled Clenshaw c_j, even parity)
__device__ float4 g_buf1[NN * F4];    // 25.6 MB  (scaled Clenshaw c_j, odd parity)
__device__ __nv_bfloat16 g_ah[NN * FIN];     // 12.8 MB  Clenshaw result, bf16 hi
__device__ __nv_bfloat16 g_al[NN * FIN];     // 12.8 MB  Clenshaw result, bf16 lo
__device__ __nv_bfloat16 g_wh[HIDN * FIN];   // W hi
__device__ __nv_bfloat16 g_wl[HIDN * FIN];   // W lo

// ---------------- generic helpers ----------------
__device__ __forceinline__ float4 f4z() { return make_float4(0.f, 0.f, 0.f, 0.f); }
__device__ __forceinline__ void f4add(float4& a, const float4& v) {
    a.x += v.x; a.y += v.y; a.z += v.z; a.w += v.w;
}
__device__ __forceinline__ int clampi(int v, int lo, int hi) {
    return min(max(v, lo), hi);
}
__device__ __forceinline__ void get_pair(const void* he, int i, int& node, int& edge) {
    if (g_flag32 == 0) { // int64
        node = (int)((const long long*)he)[i];
        edge = (int)((const long long*)he)[NZ + i];
    } else {             // int32
        node = ((const int*)he)[i];
        edge = ((const int*)he)[NZ + i];
    }
    node = clampi(node, 0, NN - 1);
    edge = clampi(edge, 0, NE - 1);
}

// mma.sync bf16 (baseline PTX, works on plain sm_103 target)
__device__ __forceinline__ void mma_bf16(float* d, const unsigned* a, const unsigned* b) {
    asm volatile(
        "mma.sync.aligned.m16n8k16.row.col.f32.bf16.bf16.f32 "
        "{%0,%1,%2,%3}, {%4,%5,%6,%7}, {%8,%9}, {%0,%1,%2,%3};"
        : "+f"(d[0]), "+f"(d[1]), "+f"(d[2]), "+f"(d[3])
        : "r"(a[0]), "r"(a[1]), "r"(a[2]), "r"(a[3]), "r"(b[0]), "r"(b[1]));
}

// cp.async 16B with zero-fill when sz==0 (baseline PTX, sm_80+)
__device__ __forceinline__ void cp_async16(unsigned dst, const void* src, unsigned sz) {
    asm volatile("cp.async.cg.shared.global [%0], [%1], 16, %2;"
                 :: "r"(dst), "l"(src), "r"(sz) : "memory");
}
#define CP_COMMIT() asm volatile("cp.async.commit_group;" ::: "memory")
#define CP_WAIT0()  asm volatile("cp.async.wait_group 0;" ::: "memory")

// ---------------- launch 0: zero counters + dtype detection ----------------
__global__ void k_zero(const int* __restrict__ he32) {
    int i = blockIdx.x * blockDim.x + threadIdx.x;
    if (i < 4096) {
        if (he32[2 * i + 1] != 0) atomicOr(&g_flag32, 1);
    }
    if (i < NE) g_cnt_e[i] = 0;
    if (i < NN) g_cnt_v[i] = 0;
}

// ---------------- launch 1: single-pass bucketed CSR build ----------------
__global__ void k_build(const void* __restrict__ he) {
    int i = blockIdx.x * blockDim.x + threadIdx.x;
    if (i >= NZ) return;
    int node, edge;
    get_pair(he, i, node, edge);
    int p = atomicAdd(&g_cnt_e[edge], 1);
    if (p < ECAP) g_ecol[edge * ECAP + p] = node;
    int q = atomicAdd(&g_cnt_v[node], 1);
    if (q < VCAP) g_vcol[node * VCAP + q] = edge;
}

// ---------------- launch 2: fused norm factors + Clenshaw init + W split ----------------
// Warp w computes d_v for node w (lane-parallel gather + shfl reduce), then all
// lanes scale their float4 of the row: c_10 = theta[10]*s*x -> buf0.
// dew (i < NE) and W bf16 split (i < HIDN*FIN) ride along on the same index space.
__global__ void k_degs_init(const float* __restrict__ ew, const float4* __restrict__ x4,
                            const float* __restrict__ theta, const float* __restrict__ W) {
    int i = blockIdx.x * blockDim.x + threadIdx.x;
    if (i < NE) {
        float de = (float)g_cnt_e[i];
        g_dew[i] = (de > 0.f) ? (ew[i] / fmaxf(de, 1e-12f)) : 0.f;
    }
    if (i < HIDN * FIN) {
        float v = W[i];
        __nv_bfloat16 h = __float2bfloat16(v);
        g_wh[i] = h;
        g_wl[i] = __float2bfloat16(v - __bfloat162float(h));
    }
    int w = i >> 5, lane = i & 31;
    if (w < NN) {
        int cnt = min(g_cnt_v[w], VCAP);
        const int* __restrict__ col = g_vcol + w * VCAP;
        float dv = 0.f;
        if (lane < cnt)      dv  = __ldg(&ew[col[lane]]);
        if (lane + 32 < cnt) dv += __ldg(&ew[col[lane + 32]]);
        #pragma unroll
        for (int d = 16; d >= 1; d >>= 1)
            dv += __shfl_xor_sync(0xffffffffu, dv, d);
        float s = (dv > 0.f) ? rsqrtf(fmaxf(dv, 1e-12f)) : 0.f;
        if (lane == 0) g_dvis[w] = s;
        float a = theta[KORD] * s;
        float4 v = x4[i];
        v.x *= a; v.y *= a; v.z *= a; v.w *= a;
        g_buf0[i] = v;   // c_10 -> buf[10&1] = buf0
    }
}

// ---------------- hot loop: edge aggregation (phase A), 4 warps per edge ----------------
// Scaled space: m_e[e,:] = de_w[e] * sum_{v in e} c_{j+1}[v,:]  (no dvis gather)
__global__ void __launch_bounds__(256, 8) k_edge(int j) {
    const float4* __restrict__ t = ((j + 1) & 1) ? g_buf1 : g_buf0;
    __shared__ float4 part[8][32];
    int tid = threadIdx.x;
    int wid = tid >> 5;
    int lane = tid & 31;
    int sub = wid >> 2;
    int chunk = wid & 3;
    int e_idx = blockIdx.x * 2 + sub;

    const int* __restrict__ col = g_ecol + e_idx * ECAP;
    int deg = min(g_cnt_e[e_idx], ECAP);

    float4 a0 = f4z(), a1 = f4z();
    int jj = chunk;
    for (; jj + 12 < deg; jj += 16) {
        int n0 = col[jj], n1 = col[jj + 4], n2 = col[jj + 8], n3 = col[jj + 12];
        float4 v0 = __ldg(&t[n0 * F4 + lane]);
        float4 v1 = __ldg(&t[n1 * F4 + lane]);
        float4 v2 = __ldg(&t[n2 * F4 + lane]);
        float4 v3 = __ldg(&t[n3 * F4 + lane]);
        f4add(a0, v0); f4add(a1, v1); f4add(a0, v2); f4add(a1, v3);
    }
    for (; jj < deg; jj += 4) {
        int n0 = col[jj];
        float4 v0 = __ldg(&t[n0 * F4 + lane]);
        f4add(a0, v0);
    }
    float4 a;
    a.x = a0.x + a1.x;
    a.y = a0.y + a1.y;
    a.z = a0.z + a1.z;
    a.w = a0.w + a1.w;
    part[wid][lane] = a;
    __syncthreads();

    if (chunk == 0) {
        int b = sub * 4;
        float4 p0 = part[b][lane], p1 = part[b + 1][lane];
        float4 p2 = part[b + 2][lane], p3 = part[b + 3][lane];
        float dw = g_dew[e_idx];
        float4 o;
        o.x = dw * ((p0.x + p1.x) + (p2.x + p3.x));
        o.y = dw * ((p0.y + p1.y) + (p2.y + p3.y));
        o.z = dw * ((p0.z + p1.z) + (p2.z + p3.z));
        o.w = dw * ((p0.w + p1.w) + (p2.w + p3.w));
        g_me[e_idx * F4 + lane] = o;
    }
}

// ---------------- hot loop: node aggregation + scaled Clenshaw step (phase B) ----------------
// j>=1: c_j = (theta_j*s)*x - (2*s^2)*sum - c_{j+2}   (in-place in buf[j&1])
// j==0: out = theta_0*x - s*sum - b_2, b_2 = (s>0 ? c_2/s : beta2*x); split to bf16 hi/lo
__global__ void __launch_bounds__(256, 8) k_node(const float4* __restrict__ x4,
                                                 const float* __restrict__ theta, int j) {
    int w = (blockIdx.x * blockDim.x + threadIdx.x) >> 5;
    int lane = threadIdx.x & 31;
    if (w >= NN) return;
    const int* __restrict__ col = g_vcol + w * VCAP;
    int e = min(g_cnt_v[w], VCAP);
    float4 a0 = f4z(), a1 = f4z();
    int jj = 0;
    for (; jj + 4 <= e; jj += 4) {
        int e0 = col[jj], e1 = col[jj + 1], e2 = col[jj + 2], e3 = col[jj + 3];
        float4 v0 = __ldg(&g_me[e0 * F4 + lane]);
        float4 v1 = __ldg(&g_me[e1 * F4 + lane]);
        float4 v2 = __ldg(&g_me[e2 * F4 + lane]);
        float4 v3 = __ldg(&g_me[e3 * F4 + lane]);
        f4add(a0, v0); f4add(a1, v1); f4add(a0, v2); f4add(a1, v3);
    }
    for (; jj < e; jj++) {
        int e0 = col[jj];
        f4add(a0, __ldg(&g_me[e0 * F4 + lane]));
    }
    float4 sum;
    sum.x = a0.x + a1.x;
    sum.y = a0.y + a1.y;
    sum.z = a0.z + a1.z;
    sum.w = a0.w + a1.w;

    float s = g_dvis[w];
    int idx = w * F4 + lane;
    float4 xv = __ldg(&x4[idx]);

    if (j == 0) {
        // out = theta0*x - s*sum - b_2
        float4 c2 = g_buf0[idx];
        float th0 = theta[0];
        float4 b2;
        if (s > 0.f) {
            float inv = 1.f / s;
            b2.x = c2.x * inv; b2.y = c2.y * inv; b2.z = c2.z * inv; b2.w = c2.w * inv;
        } else {
            float beta2 = theta[2] - theta[4] + theta[6] - theta[8] + theta[10];
            b2.x = beta2 * xv.x; b2.y = beta2 * xv.y; b2.z = beta2 * xv.z; b2.w = beta2 * xv.w;
        }
        float ms = -s;
        float4 r;
        r.x = fmaf(th0, xv.x, ms * sum.x) - b2.x;
        r.y = fmaf(th0, xv.y, ms * sum.y) - b2.y;
        r.z = fmaf(th0, xv.z, ms * sum.z) - b2.z;
        r.w = fmaf(th0, xv.w, ms * sum.w) - b2.w;
        __nv_bfloat16 h0 = __float2bfloat16(r.x);
        __nv_bfloat16 h1 = __float2bfloat16(r.y);
        __nv_bfloat16 h2 = __float2bfloat16(r.z);
        __nv_bfloat16 h3 = __float2bfloat16(r.w);
        ushort4 hh = make_ushort4(__bfloat16_as_ushort(h0), __bfloat16_as_ushort(h1),
                                  __bfloat16_as_ushort(h2), __bfloat16_as_ushort(h3));
        ushort4 ll = make_ushort4(
            __bfloat16_as_ushort(__float2bfloat16(r.x - __bfloat162float(h0))),
            __bfloat16_as_ushort(__float2bfloat16(r.y - __bfloat162float(h1))),
            __bfloat16_as_ushort(__float2bfloat16(r.z - __bfloat162float(h2))),
            __bfloat16_as_ushort(__float2bfloat16(r.w - __bfloat162float(h3))));
        *(ushort4*)(g_ah + 4 * (size_t)idx) = hh;
        *(ushort4*)(g_al + 4 * (size_t)idx) = ll;
    } else {
        float a = theta[j] * s;
        float m = -2.f * s * s;
        float4 r;
        r.x = fmaf(a, xv.x, m * sum.x);
        r.y = fmaf(a, xv.y, m * sum.y);
        r.z = fmaf(a, xv.z, m * sum.z);
        r.w = fmaf(a, xv.w, m * sum.w);
        float4* buf = (j & 1) ? g_buf1 : g_buf0;
        if (j != KORD - 1) {
            float4 old = buf[idx];
            r.x -= old.x; r.y -= old.y; r.z -= old.z; r.w -= old.w;
        }
        buf[idx] = r;
    }
}

// ---------------- GEMM (mma.sync bf16x3, cp.async pipelined) ----------------
// C = relu(A[N,128] @ W[512,128]^T + b). One CTA per 128-row block (grid=391).
// A hi/lo staged ONCE via cp.async; B tiles (128 cols) double-buffered, prefetch
// of tile ct+1 overlaps compute of tile ct. 8 warps as 4m x 2n; warp tile 32x64.
// D(fp32) = Ah*Wh + Ah*Wl + Al*Wh (Al*Wl dropped, ~2^-18 relative).
__global__ void __launch_bounds__(256) k_mma(const float* __restrict__ bias,
                                             float* __restrict__ C) {
    extern __shared__ unsigned sm[];
    unsigned* Ahs = sm;                              // GM*STRW words
    unsigned* Als = Ahs + GM * STRW;
    unsigned* Bbuf = Als + GM * STRW;                // 2 buffers x (Bh + Bl), each GNT*STRW
    int tid = threadIdx.x;
    int row0 = blockIdx.x * GM;
    unsigned smb = (unsigned)__cvta_generic_to_shared(sm);

    // --- stage A (hi/lo) via cp.async, 16B chunks, zero-fill OOB rows ---
    {
        const char* Ah8 = (const char*)g_ah;
        const char* Al8 = (const char*)g_al;
        for (int i = tid; i < GM * 16; i += 256) {
            int r = i >> 4, c4 = i & 15;             // 16 chunks of 16B per 256B row
            int gr = row0 + r;
            unsigned sz = (gr < NN) ? 16u : 0u;
            size_t gofs = (size_t)gr * 256 + c4 * 16;
            unsigned dofs = (unsigned)((r * STRW + c4 * 4) * 4);
            cp_async16(smb + ((unsigned)((char*)Ahs - (char*)sm)) + dofs, Ah8 + gofs, sz);
            cp_async16(smb + ((unsigned)((char*)Als - (char*)sm)) + dofs, Al8 + gofs, sz);
        }
    }
    // --- prefetch B tile 0 into buffer 0 (same commit group as A) ---
    const char* Wh8 = (const char*)g_wh;
    const char* Wl8 = (const char*)g_wl;
    unsigned bbase = (unsigned)((char*)Bbuf - (char*)sm);
    {
        for (int i = tid; i < GNT * 16; i += 256) {
            int r = i >> 4, c4 = i & 15;
            size_t gofs = (size_t)r * 256 + c4 * 16;   // tile 0: col0 = 0
            unsigned dofs = (unsigned)((r * STRW + c4 * 4) * 4);
            cp_async16(smb + bbase + dofs, Wh8 + gofs, 16u);
            cp_async16(smb + bbase + (unsigned)(GNT * STRW * 4) + dofs, Wl8 + gofs, 16u);
        }
    }
    CP_COMMIT();

    int wid = tid >> 5, lane = tid & 31;
    int wm = wid & 3, wn = wid >> 2;       // warp grid 4 (m) x 2 (n)
    int lr = lane >> 2, lc = lane & 3;     // m16n8k16 lane decomposition

    for (int ct = 0; ct < HIDN / GNT; ct++) {
        CP_WAIT0();
        __syncthreads();                   // tile ct data visible; compute ct-1 finished everywhere

        // prefetch tile ct+1 into the alternate buffer, overlapped with compute of ct
        if (ct + 1 < HIDN / GNT) {
            unsigned bo = bbase + (unsigned)(((ct + 1) & 1) * 2 * GNT * STRW * 4);
            size_t colbase = (size_t)(ct + 1) * GNT * 256;
            for (int i = tid; i < GNT * 16; i += 256) {
                int r = i >> 4, c4 = i & 15;
                size_t gofs = colbase + (size_t)r * 256 + c4 * 16;
                unsigned dofs = (unsigned)((r * STRW + c4 * 4) * 4);
                cp_async16(smb + bo + dofs, Wh8 + gofs, 16u);
                cp_async16(smb + bo + (unsigned)(GNT * STRW * 4) + dofs, Wl8 + gofs, 16u);
            }
            CP_COMMIT();
        }

        const unsigned* Bhs = Bbuf + (ct & 1) * 2 * GNT * STRW;
        const unsigned* Bls = Bhs + GNT * STRW;
        int col0 = ct * GNT;

        float acc[2][8][4];
        #pragma unroll
        for (int mf = 0; mf < 2; mf++)
            #pragma unroll
            for (int nf = 0; nf < 8; nf++)
                #pragma unroll
                for (int q = 0; q < 4; q++) acc[mf][nf][q] = 0.f;

        const unsigned* Aps[3] = { Ahs, Ahs, Als };
        const unsigned* Bps[3] = { Bhs, Bls, Bhs };
        #pragma unroll
        for (int ps = 0; ps < 3; ps++) {
            const unsigned* At = Aps[ps];
            const unsigned* Bt = Bps[ps];
            #pragma unroll
            for (int kk = 0; kk < 8; kk++) {   // 8 k-chunks of 16 bf16 (8 words)
                unsigned afr[2][4];
                #pragma unroll
                for (int mf = 0; mf < 2; mf++) {
                    const unsigned* p = At + (wm * 32 + mf * 16 + lr) * STRW + kk * 8 + lc;
                    afr[mf][0] = p[0];
                    afr[mf][1] = p[8 * STRW];
                    afr[mf][2] = p[4];
                    afr[mf][3] = p[8 * STRW + 4];
                }
                #pragma unroll
                for (int nf = 0; nf < 8; nf++) {
                    unsigned bfr[2];
                    const unsigned* p = Bt + (wn * 64 + nf * 8 + lr) * STRW + kk * 8 + lc;
                    bfr[0] = p[0];
                    bfr[1] = p[4];
                    mma_bf16(acc[0][nf], afr[0], bfr);
                    mma_bf16(acc[1][nf], afr[1], bfr);
                }
            }
        }

        // epilogue for this column tile: bias + relu, float2 stores
        #pragma unroll
        for (int mf = 0; mf < 2; mf++) {
            #pragma unroll
            for (int nf = 0; nf < 8; nf++) {
                int r = row0 + wm * 32 + mf * 16 + lr;
                int c = col0 + wn * 64 + nf * 8 + lc * 2;
                float2 bb = *(const float2*)&bias[c];
                if (r < NN) {
                    float2 o;
                    o.x = fmaxf(acc[mf][nf][0] + bb.x, 0.f);
                    o.y = fmaxf(acc[mf][nf][1] + bb.y, 0.f);
                    *(float2*)&C[(size_t)r * HIDN + c] = o;
                }
                int r2 = r + 8;
                if (r2 < NN) {
                    float2 o;
                    o.x = fmaxf(acc[mf][nf][2] + bb.x, 0.f);
                    o.y = fmaxf(acc[mf][nf][3] + bb.y, 0.f);
                    *(float2*)&C[(size_t)r2 * HIDN + c] = o;
                }
            }
        }
    }
}

// ---------------- launch ----------------
extern "C" void kernel_launch(void* const* d_in, const int* in_sizes, int n_in,
                              void* d_out, int out_size) {
    const float* x     = (const float*)d_in[0];
    const void*  he    = (const void*)d_in[1];
    const float* ew    = (const float*)d_in[2];
    const float* theta = (const float*)d_in[3];
    const float* w1    = (const float*)d_in[4];
    const float* b1    = (const float*)d_in[5];
    float*       out   = (float*)d_out;

    const int TB = 256;
    k_zero<<<(NN + TB - 1) / TB, TB>>>((const int*)he);
    k_build<<<(NZ + TB - 1) / TB, TB>>>(he);
    k_degs_init<<<(NN * F4 + TB - 1) / TB, TB>>>(ew, (const float4*)x, theta, w1);

    for (int j = KORD - 1; j >= 0; j--) {
        k_edge<<<NE / 2, TB>>>(j);
        k_node<<<(NN * 32 + TB - 1) / TB, TB>>>((const float4*)x, theta, j);
    }

    // SMEM: A (hi+lo) + 2 x B (hi+lo) = (2 + 4) * 128 * STRW words
    const int SMEM_MMA = (2 * GM * STRW + 4 * GNT * STRW) * 4;  // 208896 B
    cudaFuncSetAttribute(k_mma, cudaFuncAttributeMaxDynamicSharedMemorySize, SMEM_MMA);
    k_mma<<<(NN + GM - 1) / GM, 256, SMEM_MMA>>>(b1, out);
}

// round 17
// speedup vs baseline: 1.4076x; 1.0076x over previous
#include <cuda_runtime.h>
#include <cuda_bf16.h>

#define NN 50000     // nodes
#define NE 10000     // edges
#define NZ 800000    // nnz
#define FIN 128
#define F4 32        // float4 per feature row
#define HIDN 512
#define ECAP 192     // max nodes per edge bucket (Poisson(80), P(>192) ~ 1e-25)
#define VCAP 64      // max edges per node bucket (Poisson(16), P(>64) ~ 1e-20)
#define KORD 10      // Chebyshev order (theta has KORD+1 entries)
#define GM 128       // GEMM CTA tile M (rows per CTA)
#define GNT 128      // GEMM column tile (4 tiles cover HIDN=512)
#define STRW 68      // SMEM row stride in 32-bit words (64 data + 4 pad -> conflict-free frags)

// ---------------- static device scratch (no allocation allowed) ----------------
__device__ int   g_flag32 = 0;    // sticky: 1 if hyperedge_index detected as int32
__device__ int   g_cnt_e[NE];
__device__ int   g_cnt_v[NN];
__device__ int   g_ecol[NE * ECAP];   // node indices, bucketed by edge (7.7 MB)
__device__ int   g_vcol[NN * VCAP];   // edge indices, bucketed by node (12.8 MB)
__device__ float g_dvis[NN];
__device__ float g_dew[NE];
__device__ float4 g_me[NE * F4];      // 5.1 MB
__device__ float4 g_buf0[NN * F4];    // 25.6 MB  (scaled Clenshaw c_j, even parity)
__device__ float4 g_buf1[NN * F4];    // 25.6 MB  (scaled Clenshaw c_j, odd parity)
__device__ __nv_bfloat16 g_ah[NN * FIN];     // 12.8 MB  Clenshaw result, bf16 hi
__device__ __nv_bfloat16 g_al[NN * FIN];     // 12.8 MB  Clenshaw result, bf16 lo
__device__ __nv_bfloat16 g_wh[HIDN * FIN];   // W hi
__device__ __nv_bfloat16 g_wl[HIDN * FIN];   // W lo

// ---------------- generic helpers ----------------
__device__ __forceinline__ float4 f4z() { return make_float4(0.f, 0.f, 0.f, 0.f); }
__device__ __forceinline__ void f4add(float4& a, const float4& v) {
    a.x += v.x; a.y += v.y; a.z += v.z; a.w += v.w;
}
__device__ __forceinline__ int clampi(int v, int lo, int hi) {
    return min(max(v, lo), hi);
}
__device__ __forceinline__ void get_pair(const void* he, int i, int& node, int& edge) {
    if (g_flag32 == 0) { // int64
        node = (int)((const long long*)he)[i];
        edge = (int)((const long long*)he)[NZ + i];
    } else {             // int32
        node = ((const int*)he)[i];
        edge = ((const int*)he)[NZ + i];
    }
    node = clampi(node, 0, NN - 1);
    edge = clampi(edge, 0, NE - 1);
}

// mma.sync bf16 (baseline PTX, works on plain sm_103 target)
__device__ __forceinline__ void mma_bf16(float* d, const unsigned* a, const unsigned* b) {
    asm volatile(
        "mma.sync.aligned.m16n8k16.row.col.f32.bf16.bf16.f32 "
        "{%0,%1,%2,%3}, {%4,%5,%6,%7}, {%8,%9}, {%0,%1,%2,%3};"
        : "+f"(d[0]), "+f"(d[1]), "+f"(d[2]), "+f"(d[3])
        : "r"(a[0]), "r"(a[1]), "r"(a[2]), "r"(a[3]), "r"(b[0]), "r"(b[1]));
}

// cp.async 16B with zero-fill when sz==0 (baseline PTX, sm_80+)
__device__ __forceinline__ void cp_async16(unsigned dst, const void* src, unsigned sz) {
    asm volatile("cp.async.cg.shared.global [%0], [%1], 16, %2;"
                 :: "r"(dst), "l"(src), "r"(sz) : "memory");
}
#define CP_COMMIT() asm volatile("cp.async.commit_group;" ::: "memory")
#define CP_WAIT0()  asm volatile("cp.async.wait_group 0;" ::: "memory")

// ---------------- launch 0: zero counters + dtype detection ----------------
__global__ void k_zero(const int* __restrict__ he32) {
    int i = blockIdx.x * blockDim.x + threadIdx.x;
    if (i < 4096) {
        if (he32[2 * i + 1] != 0) atomicOr(&g_flag32, 1);
    }
    if (i < NE) g_cnt_e[i] = 0;
    if (i < NN) g_cnt_v[i] = 0;
}

// ---------------- launch 1: single-pass bucketed CSR build ----------------
__global__ void k_build(const void* __restrict__ he) {
    int i = blockIdx.x * blockDim.x + threadIdx.x;
    if (i >= NZ) return;
    int node, edge;
    get_pair(he, i, node, edge);
    int p = atomicAdd(&g_cnt_e[edge], 1);
    if (p < ECAP) g_ecol[edge * ECAP + p] = node;
    int q = atomicAdd(&g_cnt_v[node], 1);
    if (q < VCAP) g_vcol[node * VCAP + q] = edge;
}

// ---------------- launch 2: fused norm factors + Clenshaw init + W split ----------------
__global__ void k_degs_init(const float* __restrict__ ew, const float4* __restrict__ x4,
                            const float* __restrict__ theta, const float* __restrict__ W) {
    int i = blockIdx.x * blockDim.x + threadIdx.x;
    if (i < NE) {
        float de = (float)g_cnt_e[i];
        g_dew[i] = (de > 0.f) ? (ew[i] / fmaxf(de, 1e-12f)) : 0.f;
    }
    if (i < HIDN * FIN) {
        float v = W[i];
        __nv_bfloat16 h = __float2bfloat16(v);
        g_wh[i] = h;
        g_wl[i] = __float2bfloat16(v - __bfloat162float(h));
    }
    int w = i >> 5, lane = i & 31;
    if (w < NN) {
        int cnt = min(g_cnt_v[w], VCAP);
        const int* __restrict__ col = g_vcol + w * VCAP;
        float dv = 0.f;
        if (lane < cnt)      dv  = __ldg(&ew[col[lane]]);
        if (lane + 32 < cnt) dv += __ldg(&ew[col[lane + 32]]);
        #pragma unroll
        for (int d = 16; d >= 1; d >>= 1)
            dv += __shfl_xor_sync(0xffffffffu, dv, d);
        float s = (dv > 0.f) ? rsqrtf(fmaxf(dv, 1e-12f)) : 0.f;
        if (lane == 0) g_dvis[w] = s;
        float a = theta[KORD] * s;
        float4 v = x4[i];
        v.x *= a; v.y *= a; v.z *= a; v.w *= a;
        g_buf0[i] = v;   // c_10 -> buf[10&1] = buf0
    }
}

// ---------------- hot loop: edge aggregation (phase A), 4 warps per edge ----------------
// Scaled space: m_e[e,:] = de_w[e] * sum_{v in e} c_{j+1}[v,:]  (no dvis gather)
__global__ void __launch_bounds__(256, 8) k_edge(int j) {
    const float4* __restrict__ t = ((j + 1) & 1) ? g_buf1 : g_buf0;
    __shared__ float4 part[8][32];
    int tid = threadIdx.x;
    int wid = tid >> 5;
    int lane = tid & 31;
    int sub = wid >> 2;
    int chunk = wid & 3;
    int e_idx = blockIdx.x * 2 + sub;

    const int* __restrict__ col = g_ecol + e_idx * ECAP;
    int deg = min(g_cnt_e[e_idx], ECAP);

    float4 a0 = f4z(), a1 = f4z();
    int jj = chunk;
    for (; jj + 12 < deg; jj += 16) {
        int n0 = col[jj], n1 = col[jj + 4], n2 = col[jj + 8], n3 = col[jj + 12];
        float4 v0 = __ldg(&t[n0 * F4 + lane]);
        float4 v1 = __ldg(&t[n1 * F4 + lane]);
        float4 v2 = __ldg(&t[n2 * F4 + lane]);
        float4 v3 = __ldg(&t[n3 * F4 + lane]);
        f4add(a0, v0); f4add(a1, v1); f4add(a0, v2); f4add(a1, v3);
    }
    for (; jj < deg; jj += 4) {
        int n0 = col[jj];
        float4 v0 = __ldg(&t[n0 * F4 + lane]);
        f4add(a0, v0);
    }
    float4 a;
    a.x = a0.x + a1.x;
    a.y = a0.y + a1.y;
    a.z = a0.z + a1.z;
    a.w = a0.w + a1.w;
    part[wid][lane] = a;
    __syncthreads();

    if (chunk == 0) {
        int b = sub * 4;
        float4 p0 = part[b][lane], p1 = part[b + 1][lane];
        float4 p2 = part[b + 2][lane], p3 = part[b + 3][lane];
        float dw = g_dew[e_idx];
        float4 o;
        o.x = dw * ((p0.x + p1.x) + (p2.x + p3.x));
        o.y = dw * ((p0.y + p1.y) + (p2.y + p3.y));
        o.z = dw * ((p0.z + p1.z) + (p2.z + p3.z));
        o.w = dw * ((p0.w + p1.w) + (p2.w + p3.w));
        g_me[e_idx * F4 + lane] = o;
    }
}

// ---------------- shared: node gather of m_e (warp per node) ----------------
__device__ __forceinline__ float4 node_gather(int w, int lane) {
    const int* __restrict__ col = g_vcol + w * VCAP;
    int e = min(g_cnt_v[w], VCAP);
    float4 a0 = f4z(), a1 = f4z();
    int jj = 0;
    for (; jj + 4 <= e; jj += 4) {
        int e0 = col[jj], e1 = col[jj + 1], e2 = col[jj + 2], e3 = col[jj + 3];
        float4 v0 = __ldg(&g_me[e0 * F4 + lane]);
        float4 v1 = __ldg(&g_me[e1 * F4 + lane]);
        float4 v2 = __ldg(&g_me[e2 * F4 + lane]);
        float4 v3 = __ldg(&g_me[e3 * F4 + lane]);
        f4add(a0, v0); f4add(a1, v1); f4add(a0, v2); f4add(a1, v3);
    }
    for (; jj < e; jj++) {
        int e0 = col[jj];
        f4add(a0, __ldg(&g_me[e0 * F4 + lane]));
    }
    float4 sum;
    sum.x = a0.x + a1.x;
    sum.y = a0.y + a1.y;
    sum.z = a0.z + a1.z;
    sum.w = a0.w + a1.w;
    return sum;
}

// ---------------- hot loop: LEAN Clenshaw step (j >= 1) ----------------
// c_j = (theta_j*s)*x - (2*s^2)*sum - c_{j+2}   (in-place in buf[j&1])
__global__ void __launch_bounds__(256, 8) k_node_mid(const float4* __restrict__ x4,
                                                     const float* __restrict__ theta, int j) {
    int w = (blockIdx.x * blockDim.x + threadIdx.x) >> 5;
    int lane = threadIdx.x & 31;
    if (w >= NN) return;
    float4 sum = node_gather(w, lane);

    float s = g_dvis[w];
    int idx = w * F4 + lane;
    float4 xv = __ldg(&x4[idx]);
    float a = theta[j] * s;
    float m = -2.f * s * s;
    float4 r;
    r.x = fmaf(a, xv.x, m * sum.x);
    r.y = fmaf(a, xv.y, m * sum.y);
    r.z = fmaf(a, xv.z, m * sum.z);
    r.w = fmaf(a, xv.w, m * sum.w);
    float4* buf = (j & 1) ? g_buf1 : g_buf0;
    if (j != KORD - 1) {
        float4 old = buf[idx];
        r.x -= old.x; r.y -= old.y; r.z -= old.z; r.w -= old.w;
    }
    buf[idx] = r;
}

// ---------------- final Clenshaw step (j == 0), heavy epilogue, runs once ----------------
// out = theta_0*x - s*sum - b_2, b_2 = (s>0 ? c_2/s : beta2*x); split to bf16 hi/lo
__global__ void __launch_bounds__(256) k_node_fin(const float4* __restrict__ x4,
                                                  const float* __restrict__ theta) {
    int w = (blockIdx.x * blockDim.x + threadIdx.x) >> 5;
    int lane = threadIdx.x & 31;
    if (w >= NN) return;
    float4 sum = node_gather(w, lane);

    float s = g_dvis[w];
    int idx = w * F4 + lane;
    float4 xv = __ldg(&x4[idx]);

    float4 c2 = g_buf0[idx];
    float th0 = theta[0];
    float4 b2;
    if (s > 0.f) {
        float inv = 1.f / s;
        b2.x = c2.x * inv; b2.y = c2.y * inv; b2.z = c2.z * inv; b2.w = c2.w * inv;
    } else {
        float beta2 = theta[2] - theta[4] + theta[6] - theta[8] + theta[10];
        b2.x = beta2 * xv.x; b2.y = beta2 * xv.y; b2.z = beta2 * xv.z; b2.w = beta2 * xv.w;
    }
    float ms = -s;
    float4 r;
    r.x = fmaf(th0, xv.x, ms * sum.x) - b2.x;
    r.y = fmaf(th0, xv.y, ms * sum.y) - b2.y;
    r.z = fmaf(th0, xv.z, ms * sum.z) - b2.z;
    r.w = fmaf(th0, xv.w, ms * sum.w) - b2.w;
    __nv_bfloat16 h0 = __float2bfloat16(r.x);
    __nv_bfloat16 h1 = __float2bfloat16(r.y);
    __nv_bfloat16 h2 = __float2bfloat16(r.z);
    __nv_bfloat16 h3 = __float2bfloat16(r.w);
    ushort4 hh = make_ushort4(__bfloat16_as_ushort(h0), __bfloat16_as_ushort(h1),
                              __bfloat16_as_ushort(h2), __bfloat16_as_ushort(h3));
    ushort4 ll = make_ushort4(
        __bfloat16_as_ushort(__float2bfloat16(r.x - __bfloat162float(h0))),
        __bfloat16_as_ushort(__float2bfloat16(r.y - __bfloat162float(h1))),
        __bfloat16_as_ushort(__float2bfloat16(r.z - __bfloat162float(h2))),
        __bfloat16_as_ushort(__float2bfloat16(r.w - __bfloat162float(h3))));
    *(ushort4*)(g_ah + 4 * (size_t)idx) = hh;
    *(ushort4*)(g_al + 4 * (size_t)idx) = ll;
}

// ---------------- GEMM (mma.sync bf16x3, cp.async pipelined) ----------------
__global__ void __launch_bounds__(256) k_mma(const float* __restrict__ bias,
                                             float* __restrict__ C) {
    extern __shared__ unsigned sm[];
    unsigned* Ahs = sm;                              // GM*STRW words
    unsigned* Als = Ahs + GM * STRW;
    unsigned* Bbuf = Als + GM * STRW;                // 2 buffers x (Bh + Bl), each GNT*STRW
    int tid = threadIdx.x;
    int row0 = blockIdx.x * GM;
    unsigned smb = (unsigned)__cvta_generic_to_shared(sm);

    {
        const char* Ah8 = (const char*)g_ah;
        const char* Al8 = (const char*)g_al;
        for (int i = tid; i < GM * 16; i += 256) {
            int r = i >> 4, c4 = i & 15;
            int gr = row0 + r;
            unsigned sz = (gr < NN) ? 16u : 0u;
            size_t gofs = (size_t)gr * 256 + c4 * 16;
            unsigned dofs = (unsigned)((r * STRW + c4 * 4) * 4);
            cp_async16(smb + ((unsigned)((char*)Ahs - (char*)sm)) + dofs, Ah8 + gofs, sz);
            cp_async16(smb + ((unsigned)((char*)Als - (char*)sm)) + dofs, Al8 + gofs, sz);
        }
    }
    const char* Wh8 = (const char*)g_wh;
    const char* Wl8 = (const char*)g_wl;
    unsigned bbase = (unsigned)((char*)Bbuf - (char*)sm);
    {
        for (int i = tid; i < GNT * 16; i += 256) {
            int r = i >> 4, c4 = i & 15;
            size_t gofs = (size_t)r * 256 + c4 * 16;
            unsigned dofs = (unsigned)((r * STRW + c4 * 4) * 4);
            cp_async16(smb + bbase + dofs, Wh8 + gofs, 16u);
            cp_async16(smb + bbase + (unsigned)(GNT * STRW * 4) + dofs, Wl8 + gofs, 16u);
        }
    }
    CP_COMMIT();

    int wid = tid >> 5, lane = tid & 31;
    int wm = wid & 3, wn = wid >> 2;
    int lr = lane >> 2, lc = lane & 3;

    for (int ct = 0; ct < HIDN / GNT; ct++) {
        CP_WAIT0();
        __syncthreads();

        if (ct + 1 < HIDN / GNT) {
            unsigned bo = bbase + (unsigned)(((ct + 1) & 1) * 2 * GNT * STRW * 4);
            size_t colbase = (size_t)(ct + 1) * GNT * 256;
            for (int i = tid; i < GNT * 16; i += 256) {
                int r = i >> 4, c4 = i & 15;
                size_t gofs = colbase + (size_t)r * 256 + c4 * 16;
                unsigned dofs = (unsigned)((r * STRW + c4 * 4) * 4);
                cp_async16(smb + bo + dofs, Wh8 + gofs, 16u);
                cp_async16(smb + bo + (unsigned)(GNT * STRW * 4) + dofs, Wl8 + gofs, 16u);
            }
            CP_COMMIT();
        }

        const unsigned* Bhs = Bbuf + (ct & 1) * 2 * GNT * STRW;
        const unsigned* Bls = Bhs + GNT * STRW;
        int col0 = ct * GNT;

        float acc[2][8][4];
        #pragma unroll
        for (int mf = 0; mf < 2; mf++)
            #pragma unroll
            for (int nf = 0; nf < 8; nf++)
                #pragma unroll
                for (int q = 0; q < 4; q++) acc[mf][nf][q] = 0.f;

        const unsigned* Aps[3] = { Ahs, Ahs, Als };
        const unsigned* Bps[3] = { Bhs, Bls, Bhs };
        #pragma unroll
        for (int ps = 0; ps < 3; ps++) {
            const unsigned* At = Aps[ps];
            const unsigned* Bt = Bps[ps];
            #pragma unroll
            for (int kk = 0; kk < 8; kk++) {
                unsigned afr[2][4];
                #pragma unroll
                for (int mf = 0; mf < 2; mf++) {
                    const unsigned* p = At + (wm * 32 + mf * 16 + lr) * STRW + kk * 8 + lc;
                    afr[mf][0] = p[0];
                    afr[mf][1] = p[8 * STRW];
                    afr[mf][2] = p[4];
                    afr[mf][3] = p[8 * STRW + 4];
                }
                #pragma unroll
                for (int nf = 0; nf < 8; nf++) {
                    unsigned bfr[2];
                    const unsigned* p = Bt + (wn * 64 + nf * 8 + lr) * STRW + kk * 8 + lc;
                    bfr[0] = p[0];
                    bfr[1] = p[4];
                    mma_bf16(acc[0][nf], afr[0], bfr);
                    mma_bf16(acc[1][nf], afr[1], bfr);
                }
            }
        }

        #pragma unroll
        for (int mf = 0; mf < 2; mf++) {
            #pragma unroll
            for (int nf = 0; nf < 8; nf++) {
                int r = row0 + wm * 32 + mf * 16 + lr;
                int c = col0 + wn * 64 + nf * 8 + lc * 2;
                float2 bb = *(const float2*)&bias[c];
                if (r < NN) {
                    float2 o;
                    o.x = fmaxf(acc[mf][nf][0] + bb.x, 0.f);
                    o.y = fmaxf(acc[mf][nf][1] + bb.y, 0.f);
                    *(float2*)&C[(size_t)r * HIDN + c] = o;
                }
                int r2 = r + 8;
                if (r2 < NN) {
                    float2 o;
                    o.x = fmaxf(acc[mf][nf][2] + bb.x, 0.f);
                    o.y = fmaxf(acc[mf][nf][3] + bb.y, 0.f);
                    *(float2*)&C[(size_t)r2 * HIDN + c] = o;
                }
            }
        }
    }
}

// ---------------- launch ----------------
extern "C" void kernel_launch(void* const* d_in, const int* in_sizes, int n_in,
                              void* d_out, int out_size) {
    const float* x     = (const float*)d_in[0];
    const void*  he    = (const void*)d_in[1];
    const float* ew    = (const float*)d_in[2];
    const float* theta = (const float*)d_in[3];
    const float* w1    = (const float*)d_in[4];
    const float* b1    = (const float*)d_in[5];
    float*       out   = (float*)d_out;

    const int TB = 256;
    k_zero<<<(NN + TB - 1) / TB, TB>>>((const int*)he);
    k_build<<<(NZ + TB - 1) / TB, TB>>>(he);
    k_degs_init<<<(NN * F4 + TB - 1) / TB, TB>>>(ew, (const float4*)x, theta, w1);

    for (int j = KORD - 1; j >= 1; j--) {
        k_edge<<<NE / 2, TB>>>(j);
        k_node_mid<<<(NN * 32 + TB - 1) / TB, TB>>>((const float4*)x, theta, j);
    }
    k_edge<<<NE / 2, TB>>>(0);
    k_node_fin<<<(NN * 32 + TB - 1) / TB, TB>>>((const float4*)x, theta);

    const int SMEM_MMA = (2 * GM * STRW + 4 * GNT * STRW) * 4;  // 208896 B
    cudaFuncSetAttribute(k_mma, cudaFuncAttributeMaxDynamicSharedMemorySize, SMEM_MMA);
    k_mma<<<(NN + GM - 1) / GM, 256, SMEM_MMA>>>(b1, out);
}